// round 1
// baseline (speedup 1.0000x reference)
#include <cuda_runtime.h>
#include <cuda_bf16.h>
#include <stdint.h>

#define D_MODEL 768
#define D_FF    3072
#define MROWS   8192   // B*S = 4*2048
#define LN_EPS  1e-12f

// ---------------- scratch (__device__ globals; no runtime allocation) ----------
__device__ float          g_c[D_MODEL];
__device__ float          g_attn[(size_t)MROWS * D_MODEL];
__device__ __nv_bfloat16  g_Ah[(size_t)MROWS * D_MODEL];
__device__ __nv_bfloat16  g_Al[(size_t)MROWS * D_MODEL];
__device__ __nv_bfloat16  g_Wih[(size_t)D_FF * D_MODEL];
__device__ __nv_bfloat16  g_Wil[(size_t)D_FF * D_MODEL];
__device__ __nv_bfloat16  g_Wfh[(size_t)D_MODEL * D_FF];
__device__ __nv_bfloat16  g_Wfl[(size_t)D_MODEL * D_FF];
__device__ __nv_bfloat16  g_Hh[(size_t)MROWS * D_FF];
__device__ __nv_bfloat16  g_Hl[(size_t)MROWS * D_FF];
__device__ float          g_P[(size_t)MROWS * D_MODEL];

// ---------------- small helpers ------------------------------------------------
__device__ __forceinline__ float gelu_exact(float x) {
    return 0.5f * x * (1.0f + erff(x * 0.7071067811865476f));
}

__device__ __forceinline__ void ldsm4(uint32_t (&r)[4], uint32_t addr) {
    asm volatile("ldmatrix.sync.aligned.m8n8.x4.shared.b16 {%0,%1,%2,%3}, [%4];"
                 : "=r"(r[0]), "=r"(r[1]), "=r"(r[2]), "=r"(r[3])
                 : "r"(addr));
}

__device__ __forceinline__ void mma_bf16(float (&c)[4], const uint32_t (&a)[4],
                                         uint32_t b0, uint32_t b1) {
    asm volatile(
        "mma.sync.aligned.m16n8k16.row.col.f32.bf16.bf16.f32 "
        "{%0,%1,%2,%3},{%4,%5,%6,%7},{%8,%9},{%0,%1,%2,%3};"
        : "+f"(c[0]), "+f"(c[1]), "+f"(c[2]), "+f"(c[3])
        : "r"(a[0]), "r"(a[1]), "r"(a[2]), "r"(a[3]), "r"(b0), "r"(b1));
}

__device__ __forceinline__ void cp16(uint32_t saddr, const void* g) {
    asm volatile("cp.async.cg.shared.global [%0], [%1], 16;" ::"r"(saddr), "l"(g));
}

__device__ __forceinline__ void block_reduce2(float& s, float& s2) {
    __shared__ float red[2][8];
    #pragma unroll
    for (int o = 16; o; o >>= 1) {
        s  += __shfl_down_sync(0xffffffffu, s,  o);
        s2 += __shfl_down_sync(0xffffffffu, s2, o);
    }
    int lane = threadIdx.x & 31, w = threadIdx.x >> 5;
    if (lane == 0) { red[0][w] = s; red[1][w] = s2; }
    __syncthreads();
    if (w == 0) {
        s  = (lane < 8) ? red[0][lane] : 0.f;
        s2 = (lane < 8) ? red[1][lane] : 0.f;
        #pragma unroll
        for (int o = 4; o; o >>= 1) {
            s  += __shfl_down_sync(0xffffffffu, s,  o);
            s2 += __shfl_down_sync(0xffffffffu, s2, o);
        }
        if (lane == 0) { red[0][0] = s; red[1][0] = s2; }
    }
    __syncthreads();
    s = red[0][0];
    s2 = red[1][0];
}

// ---------------- tiny kernels --------------------------------------------------
// c[i] = 0.01 * sum_j Wo[i][j] + bo[i]   (ctx is exactly the constant 0.01)
__global__ void rowsum_kernel(const float* __restrict__ Wo, const float* __restrict__ bo) {
    int gw = (blockIdx.x * blockDim.x + threadIdx.x) >> 5;
    int lane = threadIdx.x & 31;
    if (gw >= D_MODEL) return;
    const float* r = Wo + (size_t)gw * D_MODEL;
    float s = 0.f;
    for (int j = lane; j < D_MODEL; j += 32) s += r[j];
    #pragma unroll
    for (int o = 16; o; o >>= 1) s += __shfl_down_sync(0xffffffffu, s, o);
    if (lane == 0) g_c[gw] = 0.01f * s + bo[gw];
}

// split fp32 weight into bf16 hi + bf16 lo
__global__ void split_kernel(const float* __restrict__ W, int which, int n) {
    __nv_bfloat16* Wh = which ? g_Wfh : g_Wih;
    __nv_bfloat16* Wl = which ? g_Wfl : g_Wil;
    int i = blockIdx.x * blockDim.x + threadIdx.x;
    if (i < n) {
        float x = W[i];
        __nv_bfloat16 h = __float2bfloat16(x);
        Wh[i] = h;
        Wl[i] = __float2bfloat16(x - __bfloat162float(h));
    }
}

// attn_out = LN(hidden + c), store fp32 + bf16 split
__global__ void ln1_kernel(const float* __restrict__ hidden,
                           const float* __restrict__ gam, const float* __restrict__ bet) {
    int row = blockIdx.x;
    const float* xr = hidden + (size_t)row * D_MODEL;
    float v[3], s = 0.f, s2 = 0.f;
    #pragma unroll
    for (int i = 0; i < 3; i++) {
        int j = threadIdx.x + i * 256;
        float t = xr[j] + g_c[j];
        v[i] = t; s += t; s2 += t * t;
    }
    block_reduce2(s, s2);
    float mean = s * (1.f / D_MODEL);
    float var = s2 * (1.f / D_MODEL) - mean * mean;
    float rstd = rsqrtf(var + LN_EPS);
    #pragma unroll
    for (int i = 0; i < 3; i++) {
        int j = threadIdx.x + i * 256;
        float a = (v[i] - mean) * rstd * gam[j] + bet[j];
        size_t o = (size_t)row * D_MODEL + j;
        g_attn[o] = a;
        __nv_bfloat16 h = __float2bfloat16(a);
        g_Ah[o] = h;
        g_Al[o] = __float2bfloat16(a - __bfloat162float(h));
    }
}

// out = LN(P)
__global__ void ln2_kernel(const float* __restrict__ gam, const float* __restrict__ bet,
                           float* __restrict__ out) {
    int row = blockIdx.x;
    const float* xr = g_P + (size_t)row * D_MODEL;
    float v[3], s = 0.f, s2 = 0.f;
    #pragma unroll
    for (int i = 0; i < 3; i++) {
        int j = threadIdx.x + i * 256;
        float t = xr[j];
        v[i] = t; s += t; s2 += t * t;
    }
    block_reduce2(s, s2);
    float mean = s * (1.f / D_MODEL);
    float var = s2 * (1.f / D_MODEL) - mean * mean;
    float rstd = rsqrtf(var + LN_EPS);
    #pragma unroll
    for (int i = 0; i < 3; i++) {
        int j = threadIdx.x + i * 256;
        out[(size_t)row * D_MODEL + j] = (v[i] - mean) * rstd * gam[j] + bet[j];
    }
}

// ---------------- GEMM: C = A @ B^T via bf16 split 3-pass ------------------------
// A: [M][K] (hi/lo bf16), B: [N][K] (hi/lo bf16), both K-contiguous.
// EPI==1: C = gelu(acc + bias) -> split to g_Hh/g_Hl  (K=768, N=3072)
// EPI==2: C = acc + bias + g_attn -> g_P              (K=3072, N=768)
#define BK 32
#define LDT 40                       // padded smem row (elements); 80B stride
#define TILE_B 10240                 // 128*40*2 bytes per operand tile
#define STAGE_B 40960                // 4 tiles per stage

template <int EPI>
__global__ void __launch_bounds__(256, 1) gemm_kernel(const float* __restrict__ bias) {
    const __nv_bfloat16* __restrict__ Ahp = (EPI == 1) ? g_Ah : g_Hh;
    const __nv_bfloat16* __restrict__ Alp = (EPI == 1) ? g_Al : g_Hl;
    const __nv_bfloat16* __restrict__ Bhp = (EPI == 1) ? g_Wih : g_Wfh;
    const __nv_bfloat16* __restrict__ Blp = (EPI == 1) ? g_Wil : g_Wfl;
    const int K  = (EPI == 1) ? D_MODEL : D_FF;
    const int NN = (EPI == 1) ? D_FF : D_MODEL;   // ldc

    extern __shared__ char smem[];
    const uint32_t smem_u32 = (uint32_t)__cvta_generic_to_shared(smem);

    const int tid = threadIdx.x;
    const int lane = tid & 31;
    const int warp = tid >> 5;
    const int wm = warp >> 2;        // 0..1
    const int wn = warp & 3;         // 0..3
    const int m_blk = blockIdx.y * 128;
    const int n_blk = blockIdx.x * 128;

    float acc[4][4][4];
    #pragma unroll
    for (int a = 0; a < 4; a++)
        #pragma unroll
        for (int b = 0; b < 4; b++)
            #pragma unroll
            for (int c = 0; c < 4; c++) acc[a][b][c] = 0.f;

    auto load_stage = [&](int s, int kt) {
        const int k0 = kt * BK;
        uint32_t base = smem_u32 + s * STAGE_B;
        #pragma unroll
        for (int h = 0; h < 2; ++h) {
            int c = tid + h * 256;
            int r = c >> 2, cc = c & 3;
            uint32_t so = (uint32_t)(r * LDT + cc * 8) * 2;
            size_t ga = (size_t)(m_blk + r) * K + (k0 + cc * 8);
            size_t gb = (size_t)(n_blk + r) * K + (k0 + cc * 8);
            cp16(base + so,              Ahp + ga);
            cp16(base + TILE_B + so,     Alp + ga);
            cp16(base + 2 * TILE_B + so, Bhp + gb);
            cp16(base + 3 * TILE_B + so, Blp + gb);
        }
    };

    const int KT = K / BK;
    load_stage(0, 0);
    asm volatile("cp.async.commit_group;");

    for (int kt = 0; kt < KT; ++kt) {
        const int s = kt & 1;
        if (kt + 1 < KT) {
            load_stage((kt + 1) & 1, kt + 1);
            asm volatile("cp.async.commit_group;");
            asm volatile("cp.async.wait_group 1;");
        } else {
            asm volatile("cp.async.wait_group 0;");
        }
        __syncthreads();

        uint32_t base = smem_u32 + s * STAGE_B;
        const int a_row = wm * 64 + (lane & 15);
        const int a_k = (lane >> 4) * 8;
        const int b_row = wn * 32 + (lane & 7) + ((lane >> 4) & 1) * 8;
        const int b_k = ((lane >> 3) & 1) * 8;

        #pragma unroll
        for (int ks = 0; ks < 2; ++ks) {
            const int k0 = ks * 16;
            uint32_t aH[4][4], aL[4][4], bH[2][4], bL[2][4];
            #pragma unroll
            for (int mt = 0; mt < 4; ++mt) {
                uint32_t ad = base + (uint32_t)((a_row + mt * 16) * LDT + k0 + a_k) * 2;
                ldsm4(aH[mt], ad);
                ldsm4(aL[mt], ad + TILE_B);
            }
            #pragma unroll
            for (int np = 0; np < 2; ++np) {
                uint32_t bd = base + 2 * TILE_B +
                              (uint32_t)((b_row + np * 16) * LDT + k0 + b_k) * 2;
                ldsm4(bH[np], bd);
                ldsm4(bL[np], bd + TILE_B);
            }
            #pragma unroll
            for (int mt = 0; mt < 4; ++mt)
                #pragma unroll
                for (int nt = 0; nt < 4; ++nt) {
                    uint32_t b0h = bH[nt >> 1][(nt & 1) * 2];
                    uint32_t b1h = bH[nt >> 1][(nt & 1) * 2 + 1];
                    uint32_t b0l = bL[nt >> 1][(nt & 1) * 2];
                    uint32_t b1l = bL[nt >> 1][(nt & 1) * 2 + 1];
                    mma_bf16(acc[mt][nt], aH[mt], b0h, b1h);  // Ah*Bh
                    mma_bf16(acc[mt][nt], aL[mt], b0h, b1h);  // Al*Bh
                    mma_bf16(acc[mt][nt], aH[mt], b0l, b1l);  // Ah*Bl
                }
        }
        __syncthreads();
    }

    // ---------------- epilogue ----------------
    #pragma unroll
    for (int mt = 0; mt < 4; ++mt)
        #pragma unroll
        for (int nt = 0; nt < 4; ++nt) {
            int n = n_blk + wn * 32 + nt * 8 + (lane & 3) * 2;
            float b0 = bias[n], b1 = bias[n + 1];
            #pragma unroll
            for (int h = 0; h < 2; ++h) {
                int m = m_blk + wm * 64 + mt * 16 + (lane >> 2) + h * 8;
                float x0 = acc[mt][nt][2 * h + 0] + b0;
                float x1 = acc[mt][nt][2 * h + 1] + b1;
                size_t o = (size_t)m * NN + n;
                if (EPI == 1) {
                    float g0 = gelu_exact(x0);
                    float g1 = gelu_exact(x1);
                    __nv_bfloat16 h0 = __float2bfloat16(g0);
                    __nv_bfloat16 h1 = __float2bfloat16(g1);
                    __nv_bfloat16 l0 = __float2bfloat16(g0 - __bfloat162float(h0));
                    __nv_bfloat16 l1 = __float2bfloat16(g1 - __bfloat162float(h1));
                    __nv_bfloat162 hv; hv.x = h0; hv.y = h1;
                    __nv_bfloat162 lv; lv.x = l0; lv.y = l1;
                    *reinterpret_cast<__nv_bfloat162*>(&g_Hh[o]) = hv;
                    *reinterpret_cast<__nv_bfloat162*>(&g_Hl[o]) = lv;
                } else {
                    x0 += g_attn[o];
                    x1 += g_attn[o + 1];
                    float2 v; v.x = x0; v.y = x1;
                    *reinterpret_cast<float2*>(&g_P[o]) = v;
                }
            }
        }
}

// ---------------- launch ---------------------------------------------------------
extern "C" void kernel_launch(void* const* d_in, const int* in_sizes, int n_in,
                              void* d_out, int out_size) {
    (void)in_sizes; (void)n_in; (void)out_size;
    const float* hidden = (const float*)d_in[0];
    // d_in[1..6] = Wq,bq,Wk,bk,Wv,bv — dead (q/k/v overwritten by constants)
    const float* Wo   = (const float*)d_in[7];
    const float* bo   = (const float*)d_in[8];
    const float* ln1g = (const float*)d_in[9];
    const float* ln1b = (const float*)d_in[10];
    const float* Wi   = (const float*)d_in[11];
    const float* bi   = (const float*)d_in[12];
    const float* Wf   = (const float*)d_in[13];
    const float* bf_  = (const float*)d_in[14];
    const float* ln2g = (const float*)d_in[15];
    const float* ln2b = (const float*)d_in[16];
    float* out = (float*)d_out;

    cudaFuncSetAttribute(gemm_kernel<1>, cudaFuncAttributeMaxDynamicSharedMemorySize, 2 * STAGE_B);
    cudaFuncSetAttribute(gemm_kernel<2>, cudaFuncAttributeMaxDynamicSharedMemorySize, 2 * STAGE_B);

    rowsum_kernel<<<96, 256>>>(Wo, bo);
    ln1_kernel<<<MROWS, 256>>>(hidden, ln1g, ln1b);
    const int wn_elems = D_FF * D_MODEL;
    split_kernel<<<(wn_elems + 255) / 256, 256>>>(Wi, 0, wn_elems);
    split_kernel<<<(wn_elems + 255) / 256, 256>>>(Wf, 1, wn_elems);

    gemm_kernel<1><<<dim3(D_FF / 128, MROWS / 128), 256, 2 * STAGE_B>>>(bi);
    gemm_kernel<2><<<dim3(D_MODEL / 128, MROWS / 128), 256, 2 * STAGE_B>>>(bf_);

    ln2_kernel<<<MROWS, 256>>>(ln2g, ln2b, out);
}

// round 3
// speedup vs baseline: 2.3621x; 2.3621x over previous
#include <cuda_runtime.h>
#include <cuda_fp16.h>
#include <stdint.h>

#define D_MODEL 768
#define D_FF    3072
#define MROWS   8192   // B*S = 4*2048
#define LN_EPS  1e-12f

// ---------------- scratch (__device__ globals; no runtime allocation) ----------
__device__ float   g_c[D_MODEL];
__device__ float   g_attn[(size_t)MROWS * D_MODEL];
__device__ __half  g_A[(size_t)MROWS * D_MODEL];
__device__ __half  g_Wi[(size_t)D_FF * D_MODEL];
__device__ __half  g_Wf[(size_t)D_MODEL * D_FF];
__device__ __half  g_H[(size_t)MROWS * D_FF];
__device__ float   g_P[(size_t)MROWS * D_MODEL];

// ---------------- helpers --------------------------------------------------------
__device__ __forceinline__ float gelu_exact(float x) {
    return 0.5f * x * (1.0f + erff(x * 0.7071067811865476f));
}

__device__ __forceinline__ void ldsm4(uint32_t (&r)[4], uint32_t addr) {
    asm volatile("ldmatrix.sync.aligned.m8n8.x4.shared.b16 {%0,%1,%2,%3}, [%4];"
                 : "=r"(r[0]), "=r"(r[1]), "=r"(r[2]), "=r"(r[3])
                 : "r"(addr));
}

__device__ __forceinline__ void mma_f16(float (&c)[4], const uint32_t (&a)[4],
                                        uint32_t b0, uint32_t b1) {
    asm volatile(
        "mma.sync.aligned.m16n8k16.row.col.f32.f16.f16.f32 "
        "{%0,%1,%2,%3},{%4,%5,%6,%7},{%8,%9},{%0,%1,%2,%3};"
        : "+f"(c[0]), "+f"(c[1]), "+f"(c[2]), "+f"(c[3])
        : "r"(a[0]), "r"(a[1]), "r"(a[2]), "r"(a[3]), "r"(b0), "r"(b1));
}

__device__ __forceinline__ void cp16(uint32_t saddr, const void* g) {
    asm volatile("cp.async.cg.shared.global [%0], [%1], 16;" ::"r"(saddr), "l"(g));
}

__device__ __forceinline__ void block_reduce2(float& s, float& s2) {
    __shared__ float red[2][8];
    #pragma unroll
    for (int o = 16; o; o >>= 1) {
        s  += __shfl_down_sync(0xffffffffu, s,  o);
        s2 += __shfl_down_sync(0xffffffffu, s2, o);
    }
    int lane = threadIdx.x & 31, w = threadIdx.x >> 5;
    if (lane == 0) { red[0][w] = s; red[1][w] = s2; }
    __syncthreads();
    if (w == 0) {
        s  = (lane < 8) ? red[0][lane] : 0.f;
        s2 = (lane < 8) ? red[1][lane] : 0.f;
        #pragma unroll
        for (int o = 4; o; o >>= 1) {
            s  += __shfl_down_sync(0xffffffffu, s,  o);
            s2 += __shfl_down_sync(0xffffffffu, s2, o);
        }
        if (lane == 0) { red[0][0] = s; red[1][0] = s2; }
    }
    __syncthreads();
    s = red[0][0];
    s2 = red[1][0];
}

// ---------------- tiny kernels --------------------------------------------------
// c[i] = 0.01 * sum_j Wo[i][j] + bo[i]   (ctx is exactly the constant 0.01)
__global__ void rowsum_kernel(const float* __restrict__ Wo, const float* __restrict__ bo) {
    int gw = (blockIdx.x * blockDim.x + threadIdx.x) >> 5;
    int lane = threadIdx.x & 31;
    if (gw >= D_MODEL) return;
    const float* r = Wo + (size_t)gw * D_MODEL;
    float s = 0.f;
    for (int j = lane; j < D_MODEL; j += 32) s += r[j];
    #pragma unroll
    for (int o = 16; o; o >>= 1) s += __shfl_down_sync(0xffffffffu, s, o);
    if (lane == 0) g_c[gw] = 0.01f * s + bo[gw];
}

// convert both weight matrices to fp16, float4-vectorized
__global__ void conv2_kernel(const float* __restrict__ Wi, const float* __restrict__ Wf) {
    constexpr int n4 = D_FF * D_MODEL / 4;
    int i = blockIdx.x * blockDim.x + threadIdx.x;
    const float* src;
    __half* Wh;
    int j;
    if (i < n4) { src = Wi; Wh = g_Wi; j = i; }
    else        { src = Wf; Wh = g_Wf; j = i - n4; }
    float4 v = reinterpret_cast<const float4*>(src)[j];
    __half2 h01 = __floats2half2_rn(v.x, v.y);
    __half2 h23 = __floats2half2_rn(v.z, v.w);
    uint2 hv = make_uint2(*(uint32_t*)&h01, *(uint32_t*)&h23);
    reinterpret_cast<uint2*>(Wh)[j] = hv;
}

// attn_out = LN(hidden + c), store fp32 + fp16
__global__ void ln1_kernel(const float* __restrict__ hidden,
                           const float* __restrict__ gam, const float* __restrict__ bet) {
    int row = blockIdx.x;
    const float* xr = hidden + (size_t)row * D_MODEL;
    float v[3], s = 0.f, s2 = 0.f;
    #pragma unroll
    for (int i = 0; i < 3; i++) {
        int j = threadIdx.x + i * 256;
        float t = xr[j] + g_c[j];
        v[i] = t; s += t; s2 += t * t;
    }
    block_reduce2(s, s2);
    float mean = s * (1.f / D_MODEL);
    float var = s2 * (1.f / D_MODEL) - mean * mean;
    float rstd = rsqrtf(var + LN_EPS);
    #pragma unroll
    for (int i = 0; i < 3; i++) {
        int j = threadIdx.x + i * 256;
        float a = (v[i] - mean) * rstd * gam[j] + bet[j];
        size_t o = (size_t)row * D_MODEL + j;
        g_attn[o] = a;
        g_A[o] = __float2half(a);
    }
}

// out = LN(P)
__global__ void ln2_kernel(const float* __restrict__ gam, const float* __restrict__ bet,
                           float* __restrict__ out) {
    int row = blockIdx.x;
    const float* xr = g_P + (size_t)row * D_MODEL;
    float v[3], s = 0.f, s2 = 0.f;
    #pragma unroll
    for (int i = 0; i < 3; i++) {
        int j = threadIdx.x + i * 256;
        float t = xr[j];
        v[i] = t; s += t; s2 += t * t;
    }
    block_reduce2(s, s2);
    float mean = s * (1.f / D_MODEL);
    float var = s2 * (1.f / D_MODEL) - mean * mean;
    float rstd = rsqrtf(var + LN_EPS);
    #pragma unroll
    for (int i = 0; i < 3; i++) {
        int j = threadIdx.x + i * 256;
        out[(size_t)row * D_MODEL + j] = (v[i] - mean) * rstd * gam[j] + bet[j];
    }
}

// ---------------- GEMM: C = A @ B^T, single-pass fp16 ---------------------------
// A: [M][K] fp16, B: [N][K] fp16, K-contiguous.
// EPI==1: C = gelu(acc + bias) -> g_H   (K=768,  N=3072)
// EPI==2: C = acc + bias + g_attn -> g_P (K=3072, N=768)
#define BK 32
#define LDT 40                       // padded smem row (elements); 80B stride
#define TILE_B 10240                 // 128*40*2 bytes per operand tile
#define STAGE_B 20480                // 2 tiles per stage (A, B)

template <int EPI>
__global__ void __launch_bounds__(256) gemm_kernel(const float* __restrict__ bias) {
    const __half* __restrict__ Ap = (EPI == 1) ? g_A : g_H;
    const __half* __restrict__ Bp = (EPI == 1) ? g_Wi : g_Wf;
    const int K  = (EPI == 1) ? D_MODEL : D_FF;
    const int NN = (EPI == 1) ? D_FF : D_MODEL;   // ldc

    extern __shared__ char smem[];
    const uint32_t smem_u32 = (uint32_t)__cvta_generic_to_shared(smem);

    const int tid = threadIdx.x;
    const int lane = tid & 31;
    const int warp = tid >> 5;
    const int wm = warp >> 2;        // 0..1
    const int wn = warp & 3;         // 0..3
    const int m_blk = blockIdx.y * 128;
    const int n_blk = blockIdx.x * 128;

    float acc[4][4][4];
    #pragma unroll
    for (int a = 0; a < 4; a++)
        #pragma unroll
        for (int b = 0; b < 4; b++)
            #pragma unroll
            for (int c = 0; c < 4; c++) acc[a][b][c] = 0.f;

    auto load_stage = [&](int s, int kt) {
        const int k0 = kt * BK;
        uint32_t base = smem_u32 + s * STAGE_B;
        #pragma unroll
        for (int h = 0; h < 2; ++h) {
            int c = tid + h * 256;
            int r = c >> 2, cc = c & 3;
            uint32_t so = (uint32_t)(r * LDT + cc * 8) * 2;
            size_t ga = (size_t)(m_blk + r) * K + (k0 + cc * 8);
            size_t gb = (size_t)(n_blk + r) * K + (k0 + cc * 8);
            cp16(base + so,          Ap + ga);
            cp16(base + TILE_B + so, Bp + gb);
        }
    };

    const int KT = K / BK;
    load_stage(0, 0);
    asm volatile("cp.async.commit_group;");

    for (int kt = 0; kt < KT; ++kt) {
        const int s = kt & 1;
        if (kt + 1 < KT) {
            load_stage((kt + 1) & 1, kt + 1);
            asm volatile("cp.async.commit_group;");
            asm volatile("cp.async.wait_group 1;");
        } else {
            asm volatile("cp.async.wait_group 0;");
        }
        __syncthreads();

        uint32_t base = smem_u32 + s * STAGE_B;
        const int a_row = wm * 64 + (lane & 15);
        const int a_k = (lane >> 4) * 8;
        const int b_row = wn * 32 + (lane & 7) + ((lane >> 4) & 1) * 8;
        const int b_k = ((lane >> 3) & 1) * 8;

        #pragma unroll
        for (int ks = 0; ks < 2; ++ks) {
            const int k0 = ks * 16;
            uint32_t aF[4][4], bF[2][4];
            #pragma unroll
            for (int mt = 0; mt < 4; ++mt) {
                uint32_t ad = base + (uint32_t)((a_row + mt * 16) * LDT + k0 + a_k) * 2;
                ldsm4(aF[mt], ad);
            }
            #pragma unroll
            for (int np = 0; np < 2; ++np) {
                uint32_t bd = base + TILE_B +
                              (uint32_t)((b_row + np * 16) * LDT + k0 + b_k) * 2;
                ldsm4(bF[np], bd);
            }
            #pragma unroll
            for (int mt = 0; mt < 4; ++mt)
                #pragma unroll
                for (int nt = 0; nt < 4; ++nt) {
                    uint32_t b0 = bF[nt >> 1][(nt & 1) * 2];
                    uint32_t b1 = bF[nt >> 1][(nt & 1) * 2 + 1];
                    mma_f16(acc[mt][nt], aF[mt], b0, b1);
                }
        }
        __syncthreads();
    }

    // ---------------- epilogue ----------------
    #pragma unroll
    for (int mt = 0; mt < 4; ++mt)
        #pragma unroll
        for (int nt = 0; nt < 4; ++nt) {
            int n = n_blk + wn * 32 + nt * 8 + (lane & 3) * 2;
            float b0 = bias[n], b1 = bias[n + 1];
            #pragma unroll
            for (int h = 0; h < 2; ++h) {
                int m = m_blk + wm * 64 + mt * 16 + (lane >> 2) + h * 8;
                float x0 = acc[mt][nt][2 * h + 0] + b0;
                float x1 = acc[mt][nt][2 * h + 1] + b1;
                size_t o = (size_t)m * NN + n;
                if (EPI == 1) {
                    __half2 hv = __floats2half2_rn(gelu_exact(x0), gelu_exact(x1));
                    *reinterpret_cast<__half2*>(&g_H[o]) = hv;
                } else {
                    x0 += g_attn[o];
                    x1 += g_attn[o + 1];
                    float2 v; v.x = x0; v.y = x1;
                    *reinterpret_cast<float2*>(&g_P[o]) = v;
                }
            }
        }
}

// ---------------- launch ---------------------------------------------------------
extern "C" void kernel_launch(void* const* d_in, const int* in_sizes, int n_in,
                              void* d_out, int out_size) {
    (void)in_sizes; (void)n_in; (void)out_size;
    const float* hidden = (const float*)d_in[0];
    // d_in[1..6] = Wq,bq,Wk,bk,Wv,bv — dead (q/k/v overwritten by constants)
    const float* Wo   = (const float*)d_in[7];
    const float* bo   = (const float*)d_in[8];
    const float* ln1g = (const float*)d_in[9];
    const float* ln1b = (const float*)d_in[10];
    const float* Wi   = (const float*)d_in[11];
    const float* bi   = (const float*)d_in[12];
    const float* Wf   = (const float*)d_in[13];
    const float* bf_  = (const float*)d_in[14];
    const float* ln2g = (const float*)d_in[15];
    const float* ln2b = (const float*)d_in[16];
    float* out = (float*)d_out;

    cudaFuncSetAttribute(gemm_kernel<1>, cudaFuncAttributeMaxDynamicSharedMemorySize, 2 * STAGE_B);
    cudaFuncSetAttribute(gemm_kernel<2>, cudaFuncAttributeMaxDynamicSharedMemorySize, 2 * STAGE_B);

    rowsum_kernel<<<96, 256>>>(Wo, bo);
    ln1_kernel<<<MROWS, 256>>>(hidden, ln1g, ln1b);
    conv2_kernel<<<(2 * D_FF * D_MODEL / 4) / 256, 256>>>(Wi, Wf);

    gemm_kernel<1><<<dim3(D_FF / 128, MROWS / 128), 256, 2 * STAGE_B>>>(bi);
    gemm_kernel<2><<<dim3(D_MODEL / 128, MROWS / 128), 256, 2 * STAGE_B>>>(bf_);

    ln2_kernel<<<MROWS, 256>>>(ln2g, ln2b, out);
}

// round 4
// speedup vs baseline: 2.5676x; 1.0870x over previous
#include <cuda_runtime.h>
#include <cuda_fp16.h>
#include <stdint.h>

#define D_MODEL 768
#define D_FF    3072
#define MROWS   8192   // B*S = 4*2048
#define LN_EPS  1e-12f

// ---------------- scratch (__device__ globals; no runtime allocation) ----------
__device__ float   g_c[D_MODEL];
__device__ float   g_attn[(size_t)MROWS * D_MODEL];
__device__ __half  g_A[(size_t)MROWS * D_MODEL];
__device__ __half  g_Wi[(size_t)D_FF * D_MODEL];
__device__ __half  g_Wf[(size_t)D_MODEL * D_FF];
__device__ __half  g_H[(size_t)MROWS * D_FF];
__device__ float   g_P[(size_t)MROWS * D_MODEL];

// ---------------- helpers --------------------------------------------------------
__device__ __forceinline__ float gelu_exact(float x) {
    return 0.5f * x * (1.0f + erff(x * 0.7071067811865476f));
}

__device__ __forceinline__ void ldsm4(uint32_t (&r)[4], uint32_t addr) {
    asm volatile("ldmatrix.sync.aligned.m8n8.x4.shared.b16 {%0,%1,%2,%3}, [%4];"
                 : "=r"(r[0]), "=r"(r[1]), "=r"(r[2]), "=r"(r[3])
                 : "r"(addr));
}

__device__ __forceinline__ void mma_f16(float (&c)[4], const uint32_t (&a)[4],
                                        uint32_t b0, uint32_t b1) {
    asm volatile(
        "mma.sync.aligned.m16n8k16.row.col.f32.f16.f16.f32 "
        "{%0,%1,%2,%3},{%4,%5,%6,%7},{%8,%9},{%0,%1,%2,%3};"
        : "+f"(c[0]), "+f"(c[1]), "+f"(c[2]), "+f"(c[3])
        : "r"(a[0]), "r"(a[1]), "r"(a[2]), "r"(a[3]), "r"(b0), "r"(b1));
}

__device__ __forceinline__ void cp16(uint32_t saddr, const void* g) {
    asm volatile("cp.async.cg.shared.global [%0], [%1], 16;" ::"r"(saddr), "l"(g));
}

__device__ __forceinline__ void block_reduce2(float& s, float& s2) {
    __shared__ float red[2][8];
    #pragma unroll
    for (int o = 16; o; o >>= 1) {
        s  += __shfl_down_sync(0xffffffffu, s,  o);
        s2 += __shfl_down_sync(0xffffffffu, s2, o);
    }
    int lane = threadIdx.x & 31, w = threadIdx.x >> 5;
    if (lane == 0) { red[0][w] = s; red[1][w] = s2; }
    __syncthreads();
    if (w == 0) {
        s  = (lane < 8) ? red[0][lane] : 0.f;
        s2 = (lane < 8) ? red[1][lane] : 0.f;
        #pragma unroll
        for (int o = 4; o; o >>= 1) {
            s  += __shfl_down_sync(0xffffffffu, s,  o);
            s2 += __shfl_down_sync(0xffffffffu, s2, o);
        }
        if (lane == 0) { red[0][0] = s; red[1][0] = s2; }
    }
    __syncthreads();
    s = red[0][0];
    s2 = red[1][0];
}

// ---------------- tiny kernels --------------------------------------------------
__global__ void rowsum_kernel(const float* __restrict__ Wo, const float* __restrict__ bo) {
    int gw = (blockIdx.x * blockDim.x + threadIdx.x) >> 5;
    int lane = threadIdx.x & 31;
    if (gw >= D_MODEL) return;
    const float* r = Wo + (size_t)gw * D_MODEL;
    float s = 0.f;
    for (int j = lane; j < D_MODEL; j += 32) s += r[j];
    #pragma unroll
    for (int o = 16; o; o >>= 1) s += __shfl_down_sync(0xffffffffu, s, o);
    if (lane == 0) g_c[gw] = 0.01f * s + bo[gw];
}

__global__ void conv2_kernel(const float* __restrict__ Wi, const float* __restrict__ Wf) {
    constexpr int n4 = D_FF * D_MODEL / 4;
    int i = blockIdx.x * blockDim.x + threadIdx.x;
    const float* src;
    __half* Wh;
    int j;
    if (i < n4) { src = Wi; Wh = g_Wi; j = i; }
    else        { src = Wf; Wh = g_Wf; j = i - n4; }
    float4 v = reinterpret_cast<const float4*>(src)[j];
    __half2 h01 = __floats2half2_rn(v.x, v.y);
    __half2 h23 = __floats2half2_rn(v.z, v.w);
    uint2 hv = make_uint2(*(uint32_t*)&h01, *(uint32_t*)&h23);
    reinterpret_cast<uint2*>(Wh)[j] = hv;
}

__global__ void ln1_kernel(const float* __restrict__ hidden,
                           const float* __restrict__ gam, const float* __restrict__ bet) {
    int row = blockIdx.x;
    const float* xr = hidden + (size_t)row * D_MODEL;
    float v[3], s = 0.f, s2 = 0.f;
    #pragma unroll
    for (int i = 0; i < 3; i++) {
        int j = threadIdx.x + i * 256;
        float t = xr[j] + g_c[j];
        v[i] = t; s += t; s2 += t * t;
    }
    block_reduce2(s, s2);
    float mean = s * (1.f / D_MODEL);
    float var = s2 * (1.f / D_MODEL) - mean * mean;
    float rstd = rsqrtf(var + LN_EPS);
    #pragma unroll
    for (int i = 0; i < 3; i++) {
        int j = threadIdx.x + i * 256;
        float a = (v[i] - mean) * rstd * gam[j] + bet[j];
        size_t o = (size_t)row * D_MODEL + j;
        g_attn[o] = a;
        g_A[o] = __float2half(a);
    }
}

__global__ void ln2_kernel(const float* __restrict__ gam, const float* __restrict__ bet,
                           float* __restrict__ out) {
    int row = blockIdx.x;
    const float* xr = g_P + (size_t)row * D_MODEL;
    float v[3], s = 0.f, s2 = 0.f;
    #pragma unroll
    for (int i = 0; i < 3; i++) {
        int j = threadIdx.x + i * 256;
        float t = xr[j];
        v[i] = t; s += t; s2 += t * t;
    }
    block_reduce2(s, s2);
    float mean = s * (1.f / D_MODEL);
    float var = s2 * (1.f / D_MODEL) - mean * mean;
    float rstd = rsqrtf(var + LN_EPS);
    #pragma unroll
    for (int i = 0; i < 3; i++) {
        int j = threadIdx.x + i * 256;
        out[(size_t)row * D_MODEL + j] = (v[i] - mean) * rstd * gam[j] + bet[j];
    }
}

// ---------------- GEMM: C = A @ B^T, single-pass fp16, 4-stage pipeline ---------
// A: [M][K] fp16, B: [N][K] fp16, K-contiguous.
// EPI==1: C = gelu(acc + bias) -> g_H    (K=768,  N=3072)
// EPI==2: C = acc + bias + g_attn -> g_P (K=3072, N=768)
#define BK 32
#define LDT 40                       // padded smem row (elements); 80B stride
#define TILE_B 10240                 // 128*40*2 bytes per operand tile
#define STAGE_B 20480                // 2 tiles per stage (A, B)
#define NSTAGE 4
#define SMEM_GEMM (NSTAGE * STAGE_B) // 81920

template <int EPI>
__global__ void __launch_bounds__(256, 2) gemm_kernel(const float* __restrict__ bias) {
    const __half* __restrict__ Ap = (EPI == 1) ? g_A : g_H;
    const __half* __restrict__ Bp = (EPI == 1) ? g_Wi : g_Wf;
    const int K  = (EPI == 1) ? D_MODEL : D_FF;
    const int NN = (EPI == 1) ? D_FF : D_MODEL;   // ldc

    extern __shared__ char smem[];
    const uint32_t smem_u32 = (uint32_t)__cvta_generic_to_shared(smem);

    const int tid = threadIdx.x;
    const int lane = tid & 31;
    const int warp = tid >> 5;
    const int wm = warp >> 2;        // 0..1
    const int wn = warp & 3;         // 0..3
    const int m_blk = blockIdx.y * 128;
    const int n_blk = blockIdx.x * 128;

    float acc[4][4][4];
    #pragma unroll
    for (int a = 0; a < 4; a++)
        #pragma unroll
        for (int b = 0; b < 4; b++)
            #pragma unroll
            for (int c = 0; c < 4; c++) acc[a][b][c] = 0.f;

    // per-thread load coords (hoisted)
    const int lr0 = tid >> 2, lc0 = tid & 3;
    const int lr1 = (tid + 256) >> 2, lc1 = (tid + 256) & 3;

    auto load_stage = [&](int s, int kt) {
        const int k0 = kt * BK;
        uint32_t base = smem_u32 + s * STAGE_B;
        {
            uint32_t so = (uint32_t)(lr0 * LDT + lc0 * 8) * 2;
            size_t ga = (size_t)(m_blk + lr0) * K + (k0 + lc0 * 8);
            size_t gb = (size_t)(n_blk + lr0) * K + (k0 + lc0 * 8);
            cp16(base + so,          Ap + ga);
            cp16(base + TILE_B + so, Bp + gb);
        }
        {
            uint32_t so = (uint32_t)(lr1 * LDT + lc1 * 8) * 2;
            size_t ga = (size_t)(m_blk + lr1) * K + (k0 + lc1 * 8);
            size_t gb = (size_t)(n_blk + lr1) * K + (k0 + lc1 * 8);
            cp16(base + so,          Ap + ga);
            cp16(base + TILE_B + so, Bp + gb);
        }
        asm volatile("cp.async.commit_group;");
    };

    const int KT = K / BK;
    load_stage(0, 0);
    load_stage(1, 1);
    load_stage(2, 2);

    const int a_row = wm * 64 + (lane & 15);
    const int a_k = (lane >> 4) * 8;
    const int b_row = wn * 32 + (lane & 7) + ((lane >> 4) & 1) * 8;
    const int b_k = ((lane >> 3) & 1) * 8;

    for (int kt = 0; kt < KT; ++kt) {
        const int s = kt & (NSTAGE - 1);
        if (kt < KT - 2)      asm volatile("cp.async.wait_group 2;");
        else if (kt == KT - 2) asm volatile("cp.async.wait_group 1;");
        else                   asm volatile("cp.async.wait_group 0;");
        __syncthreads();

        if (kt + 3 < KT) load_stage((kt + 3) & (NSTAGE - 1), kt + 3);

        uint32_t base = smem_u32 + s * STAGE_B;
        #pragma unroll
        for (int ks = 0; ks < 2; ++ks) {
            const int k0 = ks * 16;
            uint32_t aF[4][4], bF[2][4];
            #pragma unroll
            for (int mt = 0; mt < 4; ++mt) {
                uint32_t ad = base + (uint32_t)((a_row + mt * 16) * LDT + k0 + a_k) * 2;
                ldsm4(aF[mt], ad);
            }
            #pragma unroll
            for (int np = 0; np < 2; ++np) {
                uint32_t bd = base + TILE_B +
                              (uint32_t)((b_row + np * 16) * LDT + k0 + b_k) * 2;
                ldsm4(bF[np], bd);
            }
            #pragma unroll
            for (int mt = 0; mt < 4; ++mt)
                #pragma unroll
                for (int nt = 0; nt < 4; ++nt) {
                    uint32_t b0 = bF[nt >> 1][(nt & 1) * 2];
                    uint32_t b1 = bF[nt >> 1][(nt & 1) * 2 + 1];
                    mma_f16(acc[mt][nt], aF[mt], b0, b1);
                }
        }
    }

    // ---------------- epilogue ----------------
    #pragma unroll
    for (int mt = 0; mt < 4; ++mt)
        #pragma unroll
        for (int nt = 0; nt < 4; ++nt) {
            int n = n_blk + wn * 32 + nt * 8 + (lane & 3) * 2;
            float b0 = bias[n], b1 = bias[n + 1];
            #pragma unroll
            for (int h = 0; h < 2; ++h) {
                int m = m_blk + wm * 64 + mt * 16 + (lane >> 2) + h * 8;
                float x0 = acc[mt][nt][2 * h + 0] + b0;
                float x1 = acc[mt][nt][2 * h + 1] + b1;
                size_t o = (size_t)m * NN + n;
                if (EPI == 1) {
                    __half2 hv = __floats2half2_rn(gelu_exact(x0), gelu_exact(x1));
                    *reinterpret_cast<__half2*>(&g_H[o]) = hv;
                } else {
                    x0 += g_attn[o];
                    x1 += g_attn[o + 1];
                    float2 v; v.x = x0; v.y = x1;
                    *reinterpret_cast<float2*>(&g_P[o]) = v;
                }
            }
        }
}

// ---------------- launch ---------------------------------------------------------
extern "C" void kernel_launch(void* const* d_in, const int* in_sizes, int n_in,
                              void* d_out, int out_size) {
    (void)in_sizes; (void)n_in; (void)out_size;
    const float* hidden = (const float*)d_in[0];
    // d_in[1..6] = Wq,bq,Wk,bk,Wv,bv — dead (q/k/v overwritten by constants)
    const float* Wo   = (const float*)d_in[7];
    const float* bo   = (const float*)d_in[8];
    const float* ln1g = (const float*)d_in[9];
    const float* ln1b = (const float*)d_in[10];
    const float* Wi   = (const float*)d_in[11];
    const float* bi   = (const float*)d_in[12];
    const float* Wf   = (const float*)d_in[13];
    const float* bf_  = (const float*)d_in[14];
    const float* ln2g = (const float*)d_in[15];
    const float* ln2b = (const float*)d_in[16];
    float* out = (float*)d_out;

    cudaFuncSetAttribute(gemm_kernel<1>, cudaFuncAttributeMaxDynamicSharedMemorySize, SMEM_GEMM);
    cudaFuncSetAttribute(gemm_kernel<2>, cudaFuncAttributeMaxDynamicSharedMemorySize, SMEM_GEMM);

    rowsum_kernel<<<96, 256>>>(Wo, bo);
    ln1_kernel<<<MROWS, 256>>>(hidden, ln1g, ln1b);
    conv2_kernel<<<(2 * D_FF * D_MODEL / 4) / 256, 256>>>(Wi, Wf);

    gemm_kernel<1><<<dim3(D_FF / 128, MROWS / 128), 256, SMEM_GEMM>>>(bi);
    gemm_kernel<2><<<dim3(D_MODEL / 128, MROWS / 128), 256, SMEM_GEMM>>>(bf_);

    ln2_kernel<<<MROWS, 256>>>(ln2g, ln2b, out);
}

// round 5
// speedup vs baseline: 2.9191x; 1.1369x over previous
#include <cuda_runtime.h>
#include <cuda_fp16.h>
#include <stdint.h>

#define D_MODEL 768
#define D_FF    3072
#define MROWS   8192   // B*S = 4*2048
#define LN_EPS  1e-12f

// ---------------- scratch (__device__ globals; no runtime allocation) ----------
__device__ float   g_c[D_MODEL];
__device__ float   g_attn[(size_t)MROWS * D_MODEL];
__device__ __half  g_A[(size_t)MROWS * D_MODEL];
__device__ __half  g_Wi[(size_t)D_FF * D_MODEL];
__device__ __half  g_Wf[(size_t)D_MODEL * D_FF];
__device__ __half  g_H[(size_t)MROWS * D_FF];
__device__ float   g_P[(size_t)MROWS * D_MODEL];
__device__ float   g_P2[(size_t)MROWS * D_MODEL];

// ---------------- helpers --------------------------------------------------------
__device__ __forceinline__ float gelu_exact(float x) {
    return 0.5f * x * (1.0f + erff(x * 0.7071067811865476f));
}

__device__ __forceinline__ void ldsm4(uint32_t (&r)[4], uint32_t addr) {
    asm volatile("ldmatrix.sync.aligned.m8n8.x4.shared.b16 {%0,%1,%2,%3}, [%4];"
                 : "=r"(r[0]), "=r"(r[1]), "=r"(r[2]), "=r"(r[3])
                 : "r"(addr));
}

__device__ __forceinline__ void mma_f16(float (&c)[4], const uint32_t (&a)[4],
                                        uint32_t b0, uint32_t b1) {
    asm volatile(
        "mma.sync.aligned.m16n8k16.row.col.f32.f16.f16.f32 "
        "{%0,%1,%2,%3},{%4,%5,%6,%7},{%8,%9},{%0,%1,%2,%3};"
        : "+f"(c[0]), "+f"(c[1]), "+f"(c[2]), "+f"(c[3])
        : "r"(a[0]), "r"(a[1]), "r"(a[2]), "r"(a[3]), "r"(b0), "r"(b1));
}

__device__ __forceinline__ void cp16(uint32_t saddr, const void* g) {
    asm volatile("cp.async.cg.shared.global [%0], [%1], 16;" ::"r"(saddr), "l"(g));
}

__device__ __forceinline__ void block_reduce2(float& s, float& s2) {
    __shared__ float red[2][8];
    #pragma unroll
    for (int o = 16; o; o >>= 1) {
        s  += __shfl_down_sync(0xffffffffu, s,  o);
        s2 += __shfl_down_sync(0xffffffffu, s2, o);
    }
    int lane = threadIdx.x & 31, w = threadIdx.x >> 5;
    if (lane == 0) { red[0][w] = s; red[1][w] = s2; }
    __syncthreads();
    if (w == 0) {
        s  = (lane < 8) ? red[0][lane] : 0.f;
        s2 = (lane < 8) ? red[1][lane] : 0.f;
        #pragma unroll
        for (int o = 4; o; o >>= 1) {
            s  += __shfl_down_sync(0xffffffffu, s,  o);
            s2 += __shfl_down_sync(0xffffffffu, s2, o);
        }
        if (lane == 0) { red[0][0] = s; red[1][0] = s2; }
    }
    __syncthreads();
    s = red[0][0];
    s2 = red[1][0];
}

// ---------------- tiny kernels --------------------------------------------------
__global__ void rowsum_kernel(const float* __restrict__ Wo, const float* __restrict__ bo) {
    int gw = (blockIdx.x * blockDim.x + threadIdx.x) >> 5;
    int lane = threadIdx.x & 31;
    if (gw >= D_MODEL) return;
    const float* r = Wo + (size_t)gw * D_MODEL;
    float s = 0.f;
    for (int j = lane; j < D_MODEL; j += 32) s += r[j];
    #pragma unroll
    for (int o = 16; o; o >>= 1) s += __shfl_down_sync(0xffffffffu, s, o);
    if (lane == 0) g_c[gw] = 0.01f * s + bo[gw];
}

__global__ void conv2_kernel(const float* __restrict__ Wi, const float* __restrict__ Wf) {
    constexpr int n4 = D_FF * D_MODEL / 4;
    int i = blockIdx.x * blockDim.x + threadIdx.x;
    const float* src;
    __half* Wh;
    int j;
    if (i < n4) { src = Wi; Wh = g_Wi; j = i; }
    else        { src = Wf; Wh = g_Wf; j = i - n4; }
    float4 v = reinterpret_cast<const float4*>(src)[j];
    __half2 h01 = __floats2half2_rn(v.x, v.y);
    __half2 h23 = __floats2half2_rn(v.z, v.w);
    uint2 hv = make_uint2(*(uint32_t*)&h01, *(uint32_t*)&h23);
    reinterpret_cast<uint2*>(Wh)[j] = hv;
}

__global__ void ln1_kernel(const float* __restrict__ hidden,
                           const float* __restrict__ gam, const float* __restrict__ bet) {
    int row = blockIdx.x;
    const float* xr = hidden + (size_t)row * D_MODEL;
    float v[3], s = 0.f, s2 = 0.f;
    #pragma unroll
    for (int i = 0; i < 3; i++) {
        int j = threadIdx.x + i * 256;
        float t = xr[j] + g_c[j];
        v[i] = t; s += t; s2 += t * t;
    }
    block_reduce2(s, s2);
    float mean = s * (1.f / D_MODEL);
    float var = s2 * (1.f / D_MODEL) - mean * mean;
    float rstd = rsqrtf(var + LN_EPS);
    #pragma unroll
    for (int i = 0; i < 3; i++) {
        int j = threadIdx.x + i * 256;
        float a = (v[i] - mean) * rstd * gam[j] + bet[j];
        size_t o = (size_t)row * D_MODEL + j;
        g_attn[o] = a;
        g_A[o] = __float2half(a);
    }
}

// out = LN(P0 + P1 + attn + bf)
__global__ void ln2_kernel(const float* __restrict__ gam, const float* __restrict__ bet,
                           const float* __restrict__ bf, float* __restrict__ out) {
    int row = blockIdx.x;
    size_t ro = (size_t)row * D_MODEL;
    float v[3], s = 0.f, s2 = 0.f;
    #pragma unroll
    for (int i = 0; i < 3; i++) {
        int j = threadIdx.x + i * 256;
        float t = g_P[ro + j] + g_P2[ro + j] + g_attn[ro + j] + bf[j];
        v[i] = t; s += t; s2 += t * t;
    }
    block_reduce2(s, s2);
    float mean = s * (1.f / D_MODEL);
    float var = s2 * (1.f / D_MODEL) - mean * mean;
    float rstd = rsqrtf(var + LN_EPS);
    #pragma unroll
    for (int i = 0; i < 3; i++) {
        int j = threadIdx.x + i * 256;
        out[ro + j] = (v[i] - mean) * rstd * gam[j] + bet[j];
    }
}

// ---------------- GEMM: C = A @ B^T, fp16, 64x64 warp tile, reg-pipelined -------
// CTA tile 128x128, 128 threads (2x2 warps of 64x64), BK=64, 3-stage cp.async.
// EPI==1: C = gelu(acc + bias) -> g_H                 (K=768,  N=3072)
// EPI==2: split-K2, raw acc -> g_P (z=0) / g_P2 (z=1) (K=3072, N=768)
#define BK 64
#define LDT 72                        // padded smem row elems; 144B stride
#define TILE_B 18432                  // 128*72*2 per operand
#define STAGE_B 36864
#define NSTAGE 3
#define SMEM_GEMM (NSTAGE * STAGE_B)  // 110592

template <int EPI>
__global__ void __launch_bounds__(128, 2) gemm_kernel(const float* __restrict__ bias) {
    const __half* __restrict__ Ap = (EPI == 1) ? g_A : g_H;
    const __half* __restrict__ Bp = (EPI == 1) ? g_Wi : g_Wf;
    const int K  = (EPI == 1) ? D_MODEL : D_FF;
    const int NN = (EPI == 1) ? D_FF : D_MODEL;
    const int KT = (EPI == 1) ? (D_MODEL / BK) : (D_FF / (2 * BK));  // 12 / 24
    const int k_base = (EPI == 2) ? (int)blockIdx.z * (D_FF / 2) : 0;

    extern __shared__ char smem[];
    const uint32_t smem_u32 = (uint32_t)__cvta_generic_to_shared(smem);

    const int tid = threadIdx.x;
    const int lane = tid & 31;
    const int warp = tid >> 5;
    const int wm = warp >> 1;        // 0..1
    const int wn = warp & 1;         // 0..1
    const int m_blk = blockIdx.y * 128;
    const int n_blk = blockIdx.x * 128;

    float acc[4][8][4];
    #pragma unroll
    for (int a = 0; a < 4; a++)
        #pragma unroll
        for (int b = 0; b < 8; b++)
            #pragma unroll
            for (int c = 0; c < 4; c++) acc[a][b][c] = 0.f;

    const int lrow = tid >> 3;        // 0..15 (row block base)
    const int lcol = tid & 7;         // 0..7 (16B chunk)

    auto load_stage = [&](int s, int kt) {
        const int k0 = k_base + kt * BK + lcol * 8;
        uint32_t base = smem_u32 + s * STAGE_B + (uint32_t)(lrow * 144 + lcol * 16);
        #pragma unroll
        for (int i = 0; i < 8; ++i) {
            int r = lrow + i * 16;
            uint32_t so = base + (uint32_t)(i * 16 * 144);
            cp16(so,          Ap + (size_t)(m_blk + r) * K + k0);
            cp16(so + TILE_B, Bp + (size_t)(n_blk + r) * K + k0);
        }
        asm volatile("cp.async.commit_group;");
    };

    load_stage(0, 0);
    load_stage(1, 1);

    const int a_row = wm * 64 + (lane & 15);
    const int a_k = (lane >> 4) * 8;
    const int b_row = wn * 64 + (lane & 7) + ((lane >> 4) & 1) * 8;
    const int b_k = ((lane >> 3) & 1) * 8;

    uint32_t aF[2][4][4], bF[2][4][4];

    auto ldsm_frags = [&](int buf, uint32_t base, int ks) {
        const int k0 = ks * 16;
        #pragma unroll
        for (int mt = 0; mt < 4; ++mt)
            ldsm4(aF[buf][mt], base + (uint32_t)((a_row + mt * 16) * LDT + k0 + a_k) * 2);
        #pragma unroll
        for (int np = 0; np < 4; ++np)
            ldsm4(bF[buf][np], base + TILE_B +
                                   (uint32_t)((b_row + np * 16) * LDT + k0 + b_k) * 2);
    };

    for (int kt = 0; kt < KT; ++kt) {
        const int s = kt % NSTAGE;
        if (kt + 1 < KT) asm volatile("cp.async.wait_group 1;");
        else             asm volatile("cp.async.wait_group 0;");
        __syncthreads();

        uint32_t base = smem_u32 + s * STAGE_B;
        ldsm_frags(0, base, 0);
        if (kt + 2 < KT) load_stage((kt + 2) % NSTAGE, kt + 2);

        #pragma unroll
        for (int ks = 0; ks < 4; ++ks) {
            const int cur = ks & 1;
            if (ks < 3) ldsm_frags(cur ^ 1, base, ks + 1);
            #pragma unroll
            for (int mt = 0; mt < 4; ++mt)
                #pragma unroll
                for (int nt = 0; nt < 8; ++nt) {
                    uint32_t b0 = bF[cur][nt >> 1][(nt & 1) * 2];
                    uint32_t b1 = bF[cur][nt >> 1][(nt & 1) * 2 + 1];
                    mma_f16(acc[mt][nt], aF[cur][mt], b0, b1);
                }
        }
    }

    // ---------------- epilogue ----------------
    float* Pout = (EPI == 2 && blockIdx.z == 1) ? g_P2 : g_P;
    #pragma unroll
    for (int mt = 0; mt < 4; ++mt)
        #pragma unroll
        for (int nt = 0; nt < 8; ++nt) {
            int n = n_blk + wn * 64 + nt * 8 + (lane & 3) * 2;
            float b0 = 0.f, b1 = 0.f;
            if (EPI == 1) { b0 = bias[n]; b1 = bias[n + 1]; }
            #pragma unroll
            for (int h = 0; h < 2; ++h) {
                int m = m_blk + wm * 64 + mt * 16 + (lane >> 2) + h * 8;
                float x0 = acc[mt][nt][2 * h + 0] + b0;
                float x1 = acc[mt][nt][2 * h + 1] + b1;
                size_t o = (size_t)m * NN + n;
                if (EPI == 1) {
                    __half2 hv = __floats2half2_rn(gelu_exact(x0), gelu_exact(x1));
                    *reinterpret_cast<__half2*>(&g_H[o]) = hv;
                } else {
                    float2 v; v.x = x0; v.y = x1;
                    *reinterpret_cast<float2*>(&Pout[o]) = v;
                }
            }
        }
}

// ---------------- launch ---------------------------------------------------------
extern "C" void kernel_launch(void* const* d_in, const int* in_sizes, int n_in,
                              void* d_out, int out_size) {
    (void)in_sizes; (void)n_in; (void)out_size;
    const float* hidden = (const float*)d_in[0];
    // d_in[1..6] = Wq,bq,Wk,bk,Wv,bv — dead (q/k/v overwritten by constants)
    const float* Wo   = (const float*)d_in[7];
    const float* bo   = (const float*)d_in[8];
    const float* ln1g = (const float*)d_in[9];
    const float* ln1b = (const float*)d_in[10];
    const float* Wi   = (const float*)d_in[11];
    const float* bi   = (const float*)d_in[12];
    const float* Wf   = (const float*)d_in[13];
    const float* bf_  = (const float*)d_in[14];
    const float* ln2g = (const float*)d_in[15];
    const float* ln2b = (const float*)d_in[16];
    float* out = (float*)d_out;

    cudaFuncSetAttribute(gemm_kernel<1>, cudaFuncAttributeMaxDynamicSharedMemorySize, SMEM_GEMM);
    cudaFuncSetAttribute(gemm_kernel<2>, cudaFuncAttributeMaxDynamicSharedMemorySize, SMEM_GEMM);

    rowsum_kernel<<<96, 256>>>(Wo, bo);
    ln1_kernel<<<MROWS, 256>>>(hidden, ln1g, ln1b);
    conv2_kernel<<<(2 * D_FF * D_MODEL / 4) / 256, 256>>>(Wi, Wf);

    gemm_kernel<1><<<dim3(D_FF / 128, MROWS / 128), 128, SMEM_GEMM>>>(bi);
    gemm_kernel<2><<<dim3(D_MODEL / 128, MROWS / 128, 2), 128, SMEM_GEMM>>>(bf_);

    ln2_kernel<<<MROWS, 256>>>(ln2g, ln2b, bf_, out);
}

// round 6
// speedup vs baseline: 2.9713x; 1.0178x over previous
#include <cuda_runtime.h>
#include <cuda_fp16.h>
#include <stdint.h>

#define D_MODEL 768
#define D_FF    3072
#define MROWS   8192   // B*S = 4*2048
#define LN_EPS  1e-12f
#define GRIDP   296    // persistent CTA count (2 per SM, safe for 148-SM die)

// ---------------- scratch (__device__ globals; no runtime allocation) ----------
__device__ float   g_c[D_MODEL];
__device__ float   g_attn[(size_t)MROWS * D_MODEL];
__device__ __half  g_A[(size_t)MROWS * D_MODEL];
__device__ __half  g_Wi[(size_t)D_FF * D_MODEL];
__device__ __half  g_Wf[(size_t)D_MODEL * D_FF];
__device__ __half  g_H[(size_t)MROWS * D_FF];
__device__ float   g_P[(size_t)MROWS * D_MODEL];
__device__ float   g_P2[(size_t)MROWS * D_MODEL];
__device__ float   g_P3[(size_t)MROWS * D_MODEL];

// ---------------- helpers --------------------------------------------------------
__device__ __forceinline__ float gelu_exact(float x) {
    return 0.5f * x * (1.0f + erff(x * 0.7071067811865476f));
}

__device__ __forceinline__ void ldsm4(uint32_t (&r)[4], uint32_t addr) {
    asm volatile("ldmatrix.sync.aligned.m8n8.x4.shared.b16 {%0,%1,%2,%3}, [%4];"
                 : "=r"(r[0]), "=r"(r[1]), "=r"(r[2]), "=r"(r[3])
                 : "r"(addr));
}

__device__ __forceinline__ void mma_f16(float (&c)[4], const uint32_t (&a)[4],
                                        uint32_t b0, uint32_t b1) {
    asm volatile(
        "mma.sync.aligned.m16n8k16.row.col.f32.f16.f16.f32 "
        "{%0,%1,%2,%3},{%4,%5,%6,%7},{%8,%9},{%0,%1,%2,%3};"
        : "+f"(c[0]), "+f"(c[1]), "+f"(c[2]), "+f"(c[3])
        : "r"(a[0]), "r"(a[1]), "r"(a[2]), "r"(a[3]), "r"(b0), "r"(b1));
}

__device__ __forceinline__ void cp16(uint32_t saddr, const void* g) {
    asm volatile("cp.async.cg.shared.global [%0], [%1], 16;" ::"r"(saddr), "l"(g));
}

// block reduce for 192 threads (6 warps)
__device__ __forceinline__ void block_reduce2_192(float& s, float& s2) {
    __shared__ float red[2][6];
    #pragma unroll
    for (int o = 16; o; o >>= 1) {
        s  += __shfl_down_sync(0xffffffffu, s,  o);
        s2 += __shfl_down_sync(0xffffffffu, s2, o);
    }
    int lane = threadIdx.x & 31, w = threadIdx.x >> 5;
    if (lane == 0) { red[0][w] = s; red[1][w] = s2; }
    __syncthreads();
    if (w == 0) {
        s  = (lane < 6) ? red[0][lane] : 0.f;
        s2 = (lane < 6) ? red[1][lane] : 0.f;
        #pragma unroll
        for (int o = 4; o; o >>= 1) {
            s  += __shfl_down_sync(0xffffffffu, s,  o);
            s2 += __shfl_down_sync(0xffffffffu, s2, o);
        }
        if (lane == 0) { red[0][0] = s; red[1][0] = s2; }
    }
    __syncthreads();
    s = red[0][0];
    s2 = red[1][0];
}

// ---------------- tiny kernels --------------------------------------------------
__global__ void rowsum_kernel(const float* __restrict__ Wo, const float* __restrict__ bo) {
    int gw = (blockIdx.x * blockDim.x + threadIdx.x) >> 5;
    int lane = threadIdx.x & 31;
    if (gw >= D_MODEL) return;
    const float* r = Wo + (size_t)gw * D_MODEL;
    float s = 0.f;
    for (int j = lane; j < D_MODEL; j += 32) s += r[j];
    #pragma unroll
    for (int o = 16; o; o >>= 1) s += __shfl_down_sync(0xffffffffu, s, o);
    if (lane == 0) g_c[gw] = 0.01f * s + bo[gw];
}

__global__ void conv2_kernel(const float* __restrict__ Wi, const float* __restrict__ Wf) {
    constexpr int n4 = D_FF * D_MODEL / 4;
    int i = blockIdx.x * blockDim.x + threadIdx.x;
    const float* src;
    __half* Wh;
    int j;
    if (i < n4) { src = Wi; Wh = g_Wi; j = i; }
    else        { src = Wf; Wh = g_Wf; j = i - n4; }
    float4 v = reinterpret_cast<const float4*>(src)[j];
    __half2 h01 = __floats2half2_rn(v.x, v.y);
    __half2 h23 = __floats2half2_rn(v.z, v.w);
    uint2 hv = make_uint2(*(uint32_t*)&h01, *(uint32_t*)&h23);
    reinterpret_cast<uint2*>(Wh)[j] = hv;
}

// attn_out = LN(hidden + c); 192 threads, float4 lanes
__global__ void ln1_kernel(const float* __restrict__ hidden,
                           const float* __restrict__ gam, const float* __restrict__ bet) {
    int row = blockIdx.x;
    int j = threadIdx.x;  // 0..191
    float4 x = reinterpret_cast<const float4*>(hidden + (size_t)row * D_MODEL)[j];
    float4 c = reinterpret_cast<const float4*>(g_c)[j];
    x.x += c.x; x.y += c.y; x.z += c.z; x.w += c.w;
    float s  = x.x + x.y + x.z + x.w;
    float s2 = x.x * x.x + x.y * x.y + x.z * x.z + x.w * x.w;
    block_reduce2_192(s, s2);
    float mean = s * (1.f / D_MODEL);
    float var = s2 * (1.f / D_MODEL) - mean * mean;
    float rstd = rsqrtf(var + LN_EPS);
    float4 g = reinterpret_cast<const float4*>(gam)[j];
    float4 b = reinterpret_cast<const float4*>(bet)[j];
    float4 a;
    a.x = (x.x - mean) * rstd * g.x + b.x;
    a.y = (x.y - mean) * rstd * g.y + b.y;
    a.z = (x.z - mean) * rstd * g.z + b.z;
    a.w = (x.w - mean) * rstd * g.w + b.w;
    reinterpret_cast<float4*>(g_attn + (size_t)row * D_MODEL)[j] = a;
    __half2 h0 = __floats2half2_rn(a.x, a.y);
    __half2 h1 = __floats2half2_rn(a.z, a.w);
    reinterpret_cast<uint2*>(g_A + (size_t)row * D_MODEL)[j] =
        make_uint2(*(uint32_t*)&h0, *(uint32_t*)&h1);
}

// out = LN(P0 + P1 + P2 + attn + bf); 192 threads, float4
__global__ void ln2_kernel(const float* __restrict__ gam, const float* __restrict__ bet,
                           const float* __restrict__ bf, float* __restrict__ out) {
    int row = blockIdx.x;
    int j = threadIdx.x;
    size_t ro4 = (size_t)row * (D_MODEL / 4) + j;
    float4 p0 = reinterpret_cast<const float4*>(g_P)[ro4];
    float4 p1 = reinterpret_cast<const float4*>(g_P2)[ro4];
    float4 p2 = reinterpret_cast<const float4*>(g_P3)[ro4];
    float4 at = reinterpret_cast<const float4*>(g_attn)[ro4];
    float4 bv = reinterpret_cast<const float4*>(bf)[j];
    float4 x;
    x.x = p0.x + p1.x + p2.x + at.x + bv.x;
    x.y = p0.y + p1.y + p2.y + at.y + bv.y;
    x.z = p0.z + p1.z + p2.z + at.z + bv.z;
    x.w = p0.w + p1.w + p2.w + at.w + bv.w;
    float s  = x.x + x.y + x.z + x.w;
    float s2 = x.x * x.x + x.y * x.y + x.z * x.z + x.w * x.w;
    block_reduce2_192(s, s2);
    float mean = s * (1.f / D_MODEL);
    float var = s2 * (1.f / D_MODEL) - mean * mean;
    float rstd = rsqrtf(var + LN_EPS);
    float4 g = reinterpret_cast<const float4*>(gam)[j];
    float4 b = reinterpret_cast<const float4*>(bet)[j];
    float4 o;
    o.x = (x.x - mean) * rstd * g.x + b.x;
    o.y = (x.y - mean) * rstd * g.y + b.y;
    o.z = (x.z - mean) * rstd * g.z + b.z;
    o.w = (x.w - mean) * rstd * g.w + b.w;
    reinterpret_cast<float4*>(out)[ro4] = o;
}

// ---------------- persistent GEMM: C = A @ B^T, fp16, 64x64 warp tile -----------
// CTA tile 128x128, 128 threads, BK=64, 3-stage continuous cp.async ring with
// cross-tile prefetch (pipeline never drains between tiles).
// EPI==1: C = gelu(acc + bias) -> g_H            (K=768,  KT=12, 1536 tiles)
// EPI==2: split-K3, raw acc -> g_P/g_P2/g_P3     (Kc=1024, KT=16, 1152 tiles)
#define BK 64
#define LDT 72                        // padded smem row elems; 144B stride
#define TILE_B 18432                  // 128*72*2 per operand
#define STAGE_B 36864
#define NSTAGE 3
#define SMEM_GEMM (NSTAGE * STAGE_B)  // 110592

template <int EPI>
__global__ void __launch_bounds__(128, 2) gemm_kernel(const float* __restrict__ bias) {
    const __half* __restrict__ Ap = (EPI == 1) ? g_A : g_H;
    const __half* __restrict__ Bp = (EPI == 1) ? g_Wi : g_Wf;
    const int K  = (EPI == 1) ? D_MODEL : D_FF;
    const int NN = (EPI == 1) ? D_FF : D_MODEL;
    const int KT = (EPI == 1) ? 12 : 16;            // slabs per tile
    const int NT = (EPI == 1) ? 1536 : 1152;        // total tiles

    extern __shared__ char smem[];
    const uint32_t smem_u32 = (uint32_t)__cvta_generic_to_shared(smem);

    const int tid = threadIdx.x;
    const int lane = tid & 31;
    const int warp = tid >> 5;
    const int wm = warp >> 1;
    const int wn = warp & 1;

    int t = blockIdx.x;
    if (t >= NT) return;

    auto decode = [&](int tt, int& mb, int& nb, int& kb) {
        if (EPI == 1) { nb = (tt % 24) * 128; mb = (tt / 24) * 128; kb = 0; }
        else          { nb = (tt % 6) * 128; mb = ((tt / 6) & 63) * 128; kb = (tt / 384) * 1024; }
    };

    int m_blk, n_blk, k_base;
    decode(t, m_blk, n_blk, k_base);

    const int lrow = tid >> 3;
    const int lcol = tid & 7;

    auto load_stage = [&](int s, int kt, int mb, int nb, int kb) {
        const int k0 = kb + kt * BK + lcol * 8;
        uint32_t base = smem_u32 + s * STAGE_B + (uint32_t)(lrow * 144 + lcol * 16);
        #pragma unroll
        for (int i = 0; i < 8; ++i) {
            uint32_t so = base + (uint32_t)(i * 16 * 144);
            cp16(so,          Ap + (size_t)(mb + lrow + i * 16) * K + k0);
            cp16(so + TILE_B, Bp + (size_t)(nb + lrow + i * 16) * K + k0);
        }
    };

    // initial prefetch: slabs 0,1 of first tile
    load_stage(0, 0, m_blk, n_blk, k_base);
    asm volatile("cp.async.commit_group;");
    load_stage(1, 1, m_blk, n_blk, k_base);
    asm volatile("cp.async.commit_group;");

    const int a_row = wm * 64 + (lane & 15);
    const int a_k = (lane >> 4) * 8;
    const int b_row = wn * 64 + (lane & 7) + ((lane >> 4) & 1) * 8;
    const int b_k = ((lane >> 3) & 1) * 8;

    uint32_t aF[2][4][4], bF[2][4][4];
    auto ldsm_frags = [&](int buf, uint32_t base, int ks) {
        const int k0 = ks * 16;
        #pragma unroll
        for (int mt = 0; mt < 4; ++mt)
            ldsm4(aF[buf][mt], base + (uint32_t)((a_row + mt * 16) * LDT + k0 + a_k) * 2);
        #pragma unroll
        for (int np = 0; np < 4; ++np)
            ldsm4(bF[buf][np], base + TILE_B +
                                   (uint32_t)((b_row + np * 16) * LDT + k0 + b_k) * 2);
    };

    int cur_st = 0;
    for (;;) {
        const int t_next = t + GRIDP;
        const bool has_next = t_next < NT;
        int nm = 0, nn2 = 0, nk = 0;
        if (has_next) decode(t_next, nm, nn2, nk);

        float acc[4][8][4];
        #pragma unroll
        for (int a = 0; a < 4; a++)
            #pragma unroll
            for (int b = 0; b < 8; b++)
                #pragma unroll
                for (int c = 0; c < 4; c++) acc[a][b][c] = 0.f;

        for (int kt = 0; kt < KT; ++kt) {
            asm volatile("cp.async.wait_group 1;");
            __syncthreads();

            uint32_t base = smem_u32 + cur_st * STAGE_B;
            ldsm_frags(0, base, 0);

            // prefetch global slab +2 (possibly next tile); always commit one group
            int p_st = cur_st + 2; if (p_st >= NSTAGE) p_st -= NSTAGE;
            const int kt2 = kt + 2;
            if (kt2 < KT)        load_stage(p_st, kt2, m_blk, n_blk, k_base);
            else if (has_next)   load_stage(p_st, kt2 - KT, nm, nn2, nk);
            asm volatile("cp.async.commit_group;");

            #pragma unroll
            for (int ks = 0; ks < 4; ++ks) {
                const int cur = ks & 1;
                if (ks < 3) ldsm_frags(cur ^ 1, base, ks + 1);
                #pragma unroll
                for (int mt = 0; mt < 4; ++mt)
                    #pragma unroll
                    for (int nt = 0; nt < 8; ++nt) {
                        uint32_t b0 = bF[cur][nt >> 1][(nt & 1) * 2];
                        uint32_t b1 = bF[cur][nt >> 1][(nt & 1) * 2 + 1];
                        mma_f16(acc[mt][nt], aF[cur][mt], b0, b1);
                    }
            }
            cur_st = (cur_st + 1 == NSTAGE) ? 0 : cur_st + 1;
        }

        // ---------------- epilogue (overlaps with next tile's slab 0/1 loads) ----
        float* Pout = g_P;
        if (EPI == 2) Pout = (k_base == 0) ? g_P : (k_base == 1024 ? g_P2 : g_P3);
        #pragma unroll
        for (int mt = 0; mt < 4; ++mt)
            #pragma unroll
            for (int nt = 0; nt < 8; ++nt) {
                int n = n_blk + wn * 64 + nt * 8 + (lane & 3) * 2;
                float b0 = 0.f, b1 = 0.f;
                if (EPI == 1) { b0 = bias[n]; b1 = bias[n + 1]; }
                #pragma unroll
                for (int h = 0; h < 2; ++h) {
                    int m = m_blk + wm * 64 + mt * 16 + (lane >> 2) + h * 8;
                    float x0 = acc[mt][nt][2 * h + 0] + b0;
                    float x1 = acc[mt][nt][2 * h + 1] + b1;
                    size_t o = (size_t)m * NN + n;
                    if (EPI == 1) {
                        __half2 hv = __floats2half2_rn(gelu_exact(x0), gelu_exact(x1));
                        *reinterpret_cast<__half2*>(&g_H[o]) = hv;
                    } else {
                        float2 v; v.x = x0; v.y = x1;
                        *reinterpret_cast<float2*>(&Pout[o]) = v;
                    }
                }
            }

        if (!has_next) break;
        t = t_next; m_blk = nm; n_blk = nn2; k_base = nk;
    }
}

// ---------------- launch ---------------------------------------------------------
extern "C" void kernel_launch(void* const* d_in, const int* in_sizes, int n_in,
                              void* d_out, int out_size) {
    (void)in_sizes; (void)n_in; (void)out_size;
    const float* hidden = (const float*)d_in[0];
    // d_in[1..6] = Wq,bq,Wk,bk,Wv,bv — dead (q/k/v overwritten by constants)
    const float* Wo   = (const float*)d_in[7];
    const float* bo   = (const float*)d_in[8];
    const float* ln1g = (const float*)d_in[9];
    const float* ln1b = (const float*)d_in[10];
    const float* Wi   = (const float*)d_in[11];
    const float* bi   = (const float*)d_in[12];
    const float* Wf   = (const float*)d_in[13];
    const float* bf_  = (const float*)d_in[14];
    const float* ln2g = (const float*)d_in[15];
    const float* ln2b = (const float*)d_in[16];
    float* out = (float*)d_out;

    cudaFuncSetAttribute(gemm_kernel<1>, cudaFuncAttributeMaxDynamicSharedMemorySize, SMEM_GEMM);
    cudaFuncSetAttribute(gemm_kernel<2>, cudaFuncAttributeMaxDynamicSharedMemorySize, SMEM_GEMM);

    rowsum_kernel<<<96, 256>>>(Wo, bo);
    ln1_kernel<<<MROWS, 192>>>(hidden, ln1g, ln1b);
    conv2_kernel<<<(2 * D_FF * D_MODEL / 4) / 256, 256>>>(Wi, Wf);

    gemm_kernel<1><<<GRIDP, 128, SMEM_GEMM>>>(bi);
    gemm_kernel<2><<<GRIDP, 128, SMEM_GEMM>>>(bf_);

    ln2_kernel<<<MROWS, 192>>>(ln2g, ln2b, bf_, out);
}

// round 7
// speedup vs baseline: 3.1060x; 1.0453x over previous
#include <cuda_runtime.h>
#include <cuda_fp16.h>
#include <stdint.h>

#define D_MODEL 768
#define D_FF    3072
#define MROWS   8192   // B*S = 4*2048
#define LN_EPS  1e-12f
#define GRIDP   296    // persistent CTA count (2 per SM on 148-SM die)

// ---------------- scratch (__device__ globals; no runtime allocation) ----------
__device__ float   g_c[D_MODEL];
__device__ float   g_attn[(size_t)MROWS * D_MODEL];
__device__ __half  g_A[(size_t)MROWS * D_MODEL];
__device__ __half  g_Wi[(size_t)D_FF * D_MODEL];
__device__ __half  g_Wf[(size_t)D_MODEL * D_FF];
__device__ __half  g_H[(size_t)MROWS * D_FF];
__device__ float   g_P[(size_t)MROWS * D_MODEL];
__device__ float   g_P2[(size_t)MROWS * D_MODEL];
__device__ float   g_P3[(size_t)MROWS * D_MODEL];
__device__ unsigned g_ctr1, g_ctr2;

// ---------------- helpers --------------------------------------------------------
__device__ __forceinline__ float gelu_exact(float x) {
    return 0.5f * x * (1.0f + erff(x * 0.7071067811865476f));
}

__device__ __forceinline__ void ldsm4(uint32_t (&r)[4], uint32_t addr) {
    asm volatile("ldmatrix.sync.aligned.m8n8.x4.shared.b16 {%0,%1,%2,%3}, [%4];"
                 : "=r"(r[0]), "=r"(r[1]), "=r"(r[2]), "=r"(r[3])
                 : "r"(addr));
}

__device__ __forceinline__ void mma_f16(float (&c)[4], const uint32_t (&a)[4],
                                        uint32_t b0, uint32_t b1) {
    asm volatile(
        "mma.sync.aligned.m16n8k16.row.col.f32.f16.f16.f32 "
        "{%0,%1,%2,%3},{%4,%5,%6,%7},{%8,%9},{%0,%1,%2,%3};"
        : "+f"(c[0]), "+f"(c[1]), "+f"(c[2]), "+f"(c[3])
        : "r"(a[0]), "r"(a[1]), "r"(a[2]), "r"(a[3]), "r"(b0), "r"(b1));
}

__device__ __forceinline__ void cp16(uint32_t saddr, const void* g) {
    asm volatile("cp.async.cg.shared.global [%0], [%1], 16;" ::"r"(saddr), "l"(g));
}

// block reduce for 192 threads (6 warps)
__device__ __forceinline__ void block_reduce2_192(float& s, float& s2) {
    __shared__ float red[2][6];
    #pragma unroll
    for (int o = 16; o; o >>= 1) {
        s  += __shfl_down_sync(0xffffffffu, s,  o);
        s2 += __shfl_down_sync(0xffffffffu, s2, o);
    }
    int lane = threadIdx.x & 31, w = threadIdx.x >> 5;
    if (lane == 0) { red[0][w] = s; red[1][w] = s2; }
    __syncthreads();
    if (w == 0) {
        s  = (lane < 6) ? red[0][lane] : 0.f;
        s2 = (lane < 6) ? red[1][lane] : 0.f;
        #pragma unroll
        for (int o = 4; o; o >>= 1) {
            s  += __shfl_down_sync(0xffffffffu, s,  o);
            s2 += __shfl_down_sync(0xffffffffu, s2, o);
        }
        if (lane == 0) { red[0][0] = s; red[1][0] = s2; }
    }
    __syncthreads();
    s = red[0][0];
    s2 = red[1][0];
}

// ---------------- small kernels --------------------------------------------------
// also resets the dynamic-scheduler counters each replay
__global__ void rowsum_kernel(const float* __restrict__ Wo, const float* __restrict__ bo) {
    if (blockIdx.x == 0 && threadIdx.x == 0) { g_ctr1 = 0; g_ctr2 = 0; }
    int gw = (blockIdx.x * blockDim.x + threadIdx.x) >> 5;
    int lane = threadIdx.x & 31;
    if (gw >= D_MODEL) return;
    const float* r = Wo + (size_t)gw * D_MODEL;
    float s = 0.f;
    for (int j = lane; j < D_MODEL; j += 32) s += r[j];
    #pragma unroll
    for (int o = 16; o; o >>= 1) s += __shfl_down_sync(0xffffffffu, s, o);
    if (lane == 0) g_c[gw] = 0.01f * s + bo[gw];
}

// merged: blocks [0,MROWS) do ln1 rows; the rest convert Wi/Wf to fp16
#define CONV_BLOCKS 6144   // 2*(D_FF*D_MODEL/4)/192
__global__ void prep_kernel(const float* __restrict__ hidden,
                            const float* __restrict__ gam, const float* __restrict__ bet,
                            const float* __restrict__ Wi, const float* __restrict__ Wf) {
    int bid = blockIdx.x;
    if (bid < MROWS) {
        int row = bid;
        int j = threadIdx.x;  // 0..191
        float4 x = reinterpret_cast<const float4*>(hidden + (size_t)row * D_MODEL)[j];
        float4 c = reinterpret_cast<const float4*>(g_c)[j];
        x.x += c.x; x.y += c.y; x.z += c.z; x.w += c.w;
        float s  = x.x + x.y + x.z + x.w;
        float s2 = x.x * x.x + x.y * x.y + x.z * x.z + x.w * x.w;
        block_reduce2_192(s, s2);
        float mean = s * (1.f / D_MODEL);
        float var = s2 * (1.f / D_MODEL) - mean * mean;
        float rstd = rsqrtf(var + LN_EPS);
        float4 g = reinterpret_cast<const float4*>(gam)[j];
        float4 b = reinterpret_cast<const float4*>(bet)[j];
        float4 a;
        a.x = (x.x - mean) * rstd * g.x + b.x;
        a.y = (x.y - mean) * rstd * g.y + b.y;
        a.z = (x.z - mean) * rstd * g.z + b.z;
        a.w = (x.w - mean) * rstd * g.w + b.w;
        reinterpret_cast<float4*>(g_attn + (size_t)row * D_MODEL)[j] = a;
        __half2 h0 = __floats2half2_rn(a.x, a.y);
        __half2 h1 = __floats2half2_rn(a.z, a.w);
        reinterpret_cast<uint2*>(g_A + (size_t)row * D_MODEL)[j] =
            make_uint2(*(uint32_t*)&h0, *(uint32_t*)&h1);
    } else {
        constexpr int n4 = D_FF * D_MODEL / 4;
        int i = (bid - MROWS) * 192 + threadIdx.x;
        const float* src;
        __half* Wh;
        int j;
        if (i < n4) { src = Wi; Wh = g_Wi; j = i; }
        else        { src = Wf; Wh = g_Wf; j = i - n4; }
        float4 v = reinterpret_cast<const float4*>(src)[j];
        __half2 h01 = __floats2half2_rn(v.x, v.y);
        __half2 h23 = __floats2half2_rn(v.z, v.w);
        reinterpret_cast<uint2*>(Wh)[j] =
            make_uint2(*(uint32_t*)&h01, *(uint32_t*)&h23);
    }
}

// out = LN(P0 + P1 + P2 + attn + bf); 192 threads, float4
__global__ void ln2_kernel(const float* __restrict__ gam, const float* __restrict__ bet,
                           const float* __restrict__ bf, float* __restrict__ out) {
    int row = blockIdx.x;
    int j = threadIdx.x;
    size_t ro4 = (size_t)row * (D_MODEL / 4) + j;
    float4 p0 = reinterpret_cast<const float4*>(g_P)[ro4];
    float4 p1 = reinterpret_cast<const float4*>(g_P2)[ro4];
    float4 p2 = reinterpret_cast<const float4*>(g_P3)[ro4];
    float4 at = reinterpret_cast<const float4*>(g_attn)[ro4];
    float4 bv = reinterpret_cast<const float4*>(bf)[j];
    float4 x;
    x.x = p0.x + p1.x + p2.x + at.x + bv.x;
    x.y = p0.y + p1.y + p2.y + at.y + bv.y;
    x.z = p0.z + p1.z + p2.z + at.z + bv.z;
    x.w = p0.w + p1.w + p2.w + at.w + bv.w;
    float s  = x.x + x.y + x.z + x.w;
    float s2 = x.x * x.x + x.y * x.y + x.z * x.z + x.w * x.w;
    block_reduce2_192(s, s2);
    float mean = s * (1.f / D_MODEL);
    float var = s2 * (1.f / D_MODEL) - mean * mean;
    float rstd = rsqrtf(var + LN_EPS);
    float4 g = reinterpret_cast<const float4*>(gam)[j];
    float4 b = reinterpret_cast<const float4*>(bet)[j];
    float4 o;
    o.x = (x.x - mean) * rstd * g.x + b.x;
    o.y = (x.y - mean) * rstd * g.y + b.y;
    o.z = (x.z - mean) * rstd * g.z + b.z;
    o.w = (x.w - mean) * rstd * g.w + b.w;
    reinterpret_cast<float4*>(out)[ro4] = o;
}

// ---------------- persistent GEMM, dynamic tile scheduling ----------------------
// CTA tile 128x128, 128 threads (2x2 warps of 64x64), BK=64, 3-stage ring,
// cross-tile prefetch, atomic-counter work distribution.
// EPI==1: C = gelu(acc + bias) -> g_H            (K=768,  KT=12, 1536 tiles)
// EPI==2: split-K3, raw acc -> g_P/g_P2/g_P3     (Kc=1024, KT=16, 1152 tiles)
#define BK 64
#define LDT 72                        // padded smem row elems; 144B stride
#define TILE_B 18432                  // 128*72*2 per operand
#define STAGE_B 36864
#define NSTAGE 3
#define SMEM_GEMM (NSTAGE * STAGE_B + 16)

template <int EPI>
__global__ void __launch_bounds__(128, 2) gemm_kernel(const float* __restrict__ bias) {
    const __half* __restrict__ Ap = (EPI == 1) ? g_A : g_H;
    const __half* __restrict__ Bp = (EPI == 1) ? g_Wi : g_Wf;
    const int K  = (EPI == 1) ? D_MODEL : D_FF;
    const int NN = (EPI == 1) ? D_FF : D_MODEL;
    const int KT = (EPI == 1) ? 12 : 16;            // slabs per tile
    const int NT = (EPI == 1) ? 1536 : 1152;        // total tiles
    unsigned* ctr = (EPI == 1) ? &g_ctr1 : &g_ctr2;

    extern __shared__ char smem[];
    const uint32_t smem_u32 = (uint32_t)__cvta_generic_to_shared(smem);
    volatile unsigned* sm_next = (volatile unsigned*)(smem + NSTAGE * STAGE_B);

    const int tid = threadIdx.x;
    const int lane = tid & 31;
    const int warp = tid >> 5;
    const int wm = warp >> 1;
    const int wn = warp & 1;
    const int lrow = tid >> 3;
    const int lcol = tid & 7;

    // first tile via atomic grab
    __shared__ unsigned s_t0;
    if (tid == 0) s_t0 = atomicAdd(ctr, 1u);
    __syncthreads();
    unsigned t = s_t0;
    if (t >= (unsigned)NT) return;

    auto decode = [&](unsigned tt, int& mb, int& nb, int& kb) {
        if (EPI == 1) { nb = (tt % 24) * 128; mb = (tt / 24) * 128; kb = 0; }
        else          { nb = (tt % 6) * 128; mb = ((tt / 6) % 64) * 128; kb = (tt / 384) * 1024; }
    };

    int m_blk, n_blk, k_base;
    decode(t, m_blk, n_blk, k_base);

    // per-thread global base pointers for the current tile (k offset handled per slab)
    const __half* pA = Ap + (size_t)(m_blk + lrow) * K + lcol * 8 + k_base;
    const __half* pB = Bp + (size_t)(n_blk + lrow) * K + lcol * 8 + k_base;

    const uint32_t sm_woff = (uint32_t)(lrow * 144 + lcol * 16);

    auto load_stage = [&](int s, int koff, const __half* a, const __half* b) {
        uint32_t base = smem_u32 + s * STAGE_B + sm_woff;
        #pragma unroll
        for (int i = 0; i < 8; ++i) {
            uint32_t so = base + (uint32_t)(i * 16 * 144);
            cp16(so,          a + (size_t)(i * 16) * K + koff);
            cp16(so + TILE_B, b + (size_t)(i * 16) * K + koff);
        }
    };

    load_stage(0, 0, pA, pB);
    asm volatile("cp.async.commit_group;");
    load_stage(1, BK, pA, pB);
    asm volatile("cp.async.commit_group;");

    const int a_row = wm * 64 + (lane & 15);
    const int a_k = (lane >> 4) * 8;
    const int b_row = wn * 64 + (lane & 7) + ((lane >> 4) & 1) * 8;
    const int b_k = ((lane >> 3) & 1) * 8;

    uint32_t aF[2][4][4], bF[2][4][4];
    auto ldsm_frags = [&](int buf, uint32_t base, int ks) {
        const int k0 = ks * 16;
        #pragma unroll
        for (int mt = 0; mt < 4; ++mt)
            ldsm4(aF[buf][mt], base + (uint32_t)((a_row + mt * 16) * LDT + k0 + a_k) * 2);
        #pragma unroll
        for (int np = 0; np < 4; ++np)
            ldsm4(bF[buf][np], base + TILE_B +
                                   (uint32_t)((b_row + np * 16) * LDT + k0 + b_k) * 2);
    };

    int cur_st = 0;
    for (;;) {
        // grab next tile id early (published through smem; visible after kt=0 sync)
        if (tid == 0) sm_next[0] = atomicAdd(ctr, 1u);

        float acc[4][8][4];
        #pragma unroll
        for (int a = 0; a < 4; a++)
            #pragma unroll
            for (int b = 0; b < 8; b++)
                #pragma unroll
                for (int c = 0; c < 4; c++) acc[a][b][c] = 0.f;

        unsigned t_next = 0;
        bool has_next = false;
        int nm = 0, nn2 = 0, nk = 0;
        const __half *pAn = pA, *pBn = pB;

        for (int kt = 0; kt < KT; ++kt) {
            asm volatile("cp.async.wait_group 1;");
            __syncthreads();

            if (kt == KT - 2) {
                t_next = sm_next[0];
                has_next = t_next < (unsigned)NT;
                if (has_next) {
                    decode(t_next, nm, nn2, nk);
                    pAn = Ap + (size_t)(nm + lrow) * K + lcol * 8 + nk;
                    pBn = Bp + (size_t)(nn2 + lrow) * K + lcol * 8 + nk;
                }
            }

            uint32_t base = smem_u32 + cur_st * STAGE_B;
            ldsm_frags(0, base, 0);

            int p_st = cur_st + 2; if (p_st >= NSTAGE) p_st -= NSTAGE;
            const int kt2 = kt + 2;
            if (kt2 < KT)      load_stage(p_st, kt2 * BK, pA, pB);
            else if (kt2 >= KT && kt >= KT - 2) {
                if (has_next) load_stage(p_st, (kt2 - KT) * BK, pAn, pBn);
            }
            asm volatile("cp.async.commit_group;");

            #pragma unroll
            for (int ks = 0; ks < 4; ++ks) {
                const int cur = ks & 1;
                if (ks < 3) ldsm_frags(cur ^ 1, base, ks + 1);
                #pragma unroll
                for (int mt = 0; mt < 4; ++mt)
                    #pragma unroll
                    for (int nt = 0; nt < 8; ++nt) {
                        uint32_t b0 = bF[cur][nt >> 1][(nt & 1) * 2];
                        uint32_t b1 = bF[cur][nt >> 1][(nt & 1) * 2 + 1];
                        mma_f16(acc[mt][nt], aF[cur][mt], b0, b1);
                    }
            }
            cur_st = (cur_st + 1 == NSTAGE) ? 0 : cur_st + 1;
        }

        // ---------------- epilogue ----------------
        float* Pout = g_P;
        if (EPI == 2) Pout = (k_base == 0) ? g_P : (k_base == 1024 ? g_P2 : g_P3);
        #pragma unroll
        for (int mt = 0; mt < 4; ++mt)
            #pragma unroll
            for (int nt = 0; nt < 8; ++nt) {
                int n = n_blk + wn * 64 + nt * 8 + (lane & 3) * 2;
                float b0 = 0.f, b1 = 0.f;
                if (EPI == 1) { b0 = bias[n]; b1 = bias[n + 1]; }
                #pragma unroll
                for (int h = 0; h < 2; ++h) {
                    int m = m_blk + wm * 64 + mt * 16 + (lane >> 2) + h * 8;
                    float x0 = acc[mt][nt][2 * h + 0] + b0;
                    float x1 = acc[mt][nt][2 * h + 1] + b1;
                    size_t o = (size_t)m * NN + n;
                    if (EPI == 1) {
                        __half2 hv = __floats2half2_rn(gelu_exact(x0), gelu_exact(x1));
                        *reinterpret_cast<__half2*>(&g_H[o]) = hv;
                    } else {
                        float2 v; v.x = x0; v.y = x1;
                        *reinterpret_cast<float2*>(&Pout[o]) = v;
                    }
                }
            }

        if (!has_next) break;
        t = t_next; m_blk = nm; n_blk = nn2; k_base = nk;
        pA = pAn; pB = pBn;
    }
}

// ---------------- launch ---------------------------------------------------------
extern "C" void kernel_launch(void* const* d_in, const int* in_sizes, int n_in,
                              void* d_out, int out_size) {
    (void)in_sizes; (void)n_in; (void)out_size;
    const float* hidden = (const float*)d_in[0];
    // d_in[1..6] = Wq,bq,Wk,bk,Wv,bv — dead (q/k/v overwritten by constants)
    const float* Wo   = (const float*)d_in[7];
    const float* bo   = (const float*)d_in[8];
    const float* ln1g = (const float*)d_in[9];
    const float* ln1b = (const float*)d_in[10];
    const float* Wi   = (const float*)d_in[11];
    const float* bi   = (const float*)d_in[12];
    const float* Wf   = (const float*)d_in[13];
    const float* bf_  = (const float*)d_in[14];
    const float* ln2g = (const float*)d_in[15];
    const float* ln2b = (const float*)d_in[16];
    float* out = (float*)d_out;

    cudaFuncSetAttribute(gemm_kernel<1>, cudaFuncAttributeMaxDynamicSharedMemorySize, SMEM_GEMM);
    cudaFuncSetAttribute(gemm_kernel<2>, cudaFuncAttributeMaxDynamicSharedMemorySize, SMEM_GEMM);

    rowsum_kernel<<<96, 256>>>(Wo, bo);
    prep_kernel<<<MROWS + CONV_BLOCKS, 192>>>(hidden, ln1g, ln1b, Wi, Wf);

    gemm_kernel<1><<<GRIDP, 128, SMEM_GEMM>>>(bi);
    gemm_kernel<2><<<GRIDP, 128, SMEM_GEMM>>>(bf_);

    ln2_kernel<<<MROWS, 192>>>(ln2g, ln2b, bf_, out);
}

// round 8
// speedup vs baseline: 3.7299x; 1.2009x over previous
#include <cuda_runtime.h>
#include <cuda_fp16.h>
#include <stdint.h>

#define D_MODEL 768
#define D_FF    3072
#define MROWS   8192   // B*S = 4*2048
#define LN_EPS  1e-12f
#define GRIDP   296    // persistent CTA count (2 per SM on 148-SM die)

// ---------------- scratch (__device__ globals; no runtime allocation) ----------
__device__ float   g_c[D_MODEL];
__device__ float   g_attn[(size_t)MROWS * D_MODEL];
__device__ __half  g_A[(size_t)MROWS * D_MODEL];
__device__ __half  g_Wi[(size_t)D_FF * D_MODEL];
__device__ __half  g_Wf[(size_t)D_MODEL * D_FF];
__device__ __half  g_H[(size_t)MROWS * D_FF];
__device__ float   g_P[(size_t)MROWS * D_MODEL];
__device__ float   g_P2[(size_t)MROWS * D_MODEL];
__device__ float   g_P3[(size_t)MROWS * D_MODEL];
__device__ unsigned g_ctr1, g_ctr2;

// ---------------- helpers --------------------------------------------------------
__device__ __forceinline__ float gelu_exact(float x) {
    return 0.5f * x * (1.0f + erff(x * 0.7071067811865476f));
}

__device__ __forceinline__ void ldsm4(uint32_t (&r)[4], uint32_t addr) {
    asm volatile("ldmatrix.sync.aligned.m8n8.x4.shared.b16 {%0,%1,%2,%3}, [%4];"
                 : "=r"(r[0]), "=r"(r[1]), "=r"(r[2]), "=r"(r[3])
                 : "r"(addr));
}

__device__ __forceinline__ void mma_f16(float (&c)[4], const uint32_t (&a)[4],
                                        uint32_t b0, uint32_t b1) {
    asm volatile(
        "mma.sync.aligned.m16n8k16.row.col.f32.f16.f16.f32 "
        "{%0,%1,%2,%3},{%4,%5,%6,%7},{%8,%9},{%0,%1,%2,%3};"
        : "+f"(c[0]), "+f"(c[1]), "+f"(c[2]), "+f"(c[3])
        : "r"(a[0]), "r"(a[1]), "r"(a[2]), "r"(a[3]), "r"(b0), "r"(b1));
}

__device__ __forceinline__ void cp16(uint32_t saddr, const void* g) {
    asm volatile("cp.async.cg.shared.global [%0], [%1], 16;" ::"r"(saddr), "l"(g));
}

// block reduce for 192 threads (6 warps)
__device__ __forceinline__ void block_reduce2_192(float& s, float& s2) {
    __shared__ float red[2][6];
    #pragma unroll
    for (int o = 16; o; o >>= 1) {
        s  += __shfl_down_sync(0xffffffffu, s,  o);
        s2 += __shfl_down_sync(0xffffffffu, s2, o);
    }
    int lane = threadIdx.x & 31, w = threadIdx.x >> 5;
    if (lane == 0) { red[0][w] = s; red[1][w] = s2; }
    __syncthreads();
    if (w == 0) {
        s  = (lane < 6) ? red[0][lane] : 0.f;
        s2 = (lane < 6) ? red[1][lane] : 0.f;
        #pragma unroll
        for (int o = 4; o; o >>= 1) {
            s  += __shfl_down_sync(0xffffffffu, s,  o);
            s2 += __shfl_down_sync(0xffffffffu, s2, o);
        }
        if (lane == 0) { red[0][0] = s; red[1][0] = s2; }
    }
    __syncthreads();
    s = red[0][0];
    s2 = red[1][0];
}

// ---------------- small kernels --------------------------------------------------
// also resets the dynamic-scheduler counters each replay
__global__ void rowsum_kernel(const float* __restrict__ Wo, const float* __restrict__ bo) {
    if (blockIdx.x == 0 && threadIdx.x == 0) { g_ctr1 = 0; g_ctr2 = 0; }
    int gw = (blockIdx.x * blockDim.x + threadIdx.x) >> 5;
    int lane = threadIdx.x & 31;
    if (gw >= D_MODEL) return;
    const float* r = Wo + (size_t)gw * D_MODEL;
    float s = 0.f;
    for (int j = lane; j < D_MODEL; j += 32) s += r[j];
    #pragma unroll
    for (int o = 16; o; o >>= 1) s += __shfl_down_sync(0xffffffffu, s, o);
    if (lane == 0) g_c[gw] = 0.01f * s + bo[gw];
}

// merged: blocks [0,MROWS) do ln1 rows; the rest convert Wi/Wf to fp16
#define CONV_BLOCKS 6144   // 2*(D_FF*D_MODEL/4)/192
__global__ void prep_kernel(const float* __restrict__ hidden,
                            const float* __restrict__ gam, const float* __restrict__ bet,
                            const float* __restrict__ Wi, const float* __restrict__ Wf) {
    int bid = blockIdx.x;
    if (bid < MROWS) {
        int row = bid;
        int j = threadIdx.x;  // 0..191
        float4 x = reinterpret_cast<const float4*>(hidden + (size_t)row * D_MODEL)[j];
        float4 c = reinterpret_cast<const float4*>(g_c)[j];
        x.x += c.x; x.y += c.y; x.z += c.z; x.w += c.w;
        float s  = x.x + x.y + x.z + x.w;
        float s2 = x.x * x.x + x.y * x.y + x.z * x.z + x.w * x.w;
        block_reduce2_192(s, s2);
        float mean = s * (1.f / D_MODEL);
        float var = s2 * (1.f / D_MODEL) - mean * mean;
        float rstd = rsqrtf(var + LN_EPS);
        float4 g = reinterpret_cast<const float4*>(gam)[j];
        float4 b = reinterpret_cast<const float4*>(bet)[j];
        float4 a;
        a.x = (x.x - mean) * rstd * g.x + b.x;
        a.y = (x.y - mean) * rstd * g.y + b.y;
        a.z = (x.z - mean) * rstd * g.z + b.z;
        a.w = (x.w - mean) * rstd * g.w + b.w;
        reinterpret_cast<float4*>(g_attn + (size_t)row * D_MODEL)[j] = a;
        __half2 h0 = __floats2half2_rn(a.x, a.y);
        __half2 h1 = __floats2half2_rn(a.z, a.w);
        reinterpret_cast<uint2*>(g_A + (size_t)row * D_MODEL)[j] =
            make_uint2(*(uint32_t*)&h0, *(uint32_t*)&h1);
    } else {
        constexpr int n4 = D_FF * D_MODEL / 4;
        int i = (bid - MROWS) * 192 + threadIdx.x;
        const float* src;
        __half* Wh;
        int j;
        if (i < n4) { src = Wi; Wh = g_Wi; j = i; }
        else        { src = Wf; Wh = g_Wf; j = i - n4; }
        float4 v = reinterpret_cast<const float4*>(src)[j];
        __half2 h01 = __floats2half2_rn(v.x, v.y);
        __half2 h23 = __floats2half2_rn(v.z, v.w);
        reinterpret_cast<uint2*>(Wh)[j] =
            make_uint2(*(uint32_t*)&h01, *(uint32_t*)&h23);
    }
}

// out = LN(P0 + P1 + P2 + attn + bf); 192 threads, float4
__global__ void ln2_kernel(const float* __restrict__ gam, const float* __restrict__ bet,
                           const float* __restrict__ bf, float* __restrict__ out) {
    int row = blockIdx.x;
    int j = threadIdx.x;
    size_t ro4 = (size_t)row * (D_MODEL / 4) + j;
    float4 p0 = reinterpret_cast<const float4*>(g_P)[ro4];
    float4 p1 = reinterpret_cast<const float4*>(g_P2)[ro4];
    float4 p2 = reinterpret_cast<const float4*>(g_P3)[ro4];
    float4 at = reinterpret_cast<const float4*>(g_attn)[ro4];
    float4 bv = reinterpret_cast<const float4*>(bf)[j];
    float4 x;
    x.x = p0.x + p1.x + p2.x + at.x + bv.x;
    x.y = p0.y + p1.y + p2.y + at.y + bv.y;
    x.z = p0.z + p1.z + p2.z + at.z + bv.z;
    x.w = p0.w + p1.w + p2.w + at.w + bv.w;
    float s  = x.x + x.y + x.z + x.w;
    float s2 = x.x * x.x + x.y * x.y + x.z * x.z + x.w * x.w;
    block_reduce2_192(s, s2);
    float mean = s * (1.f / D_MODEL);
    float var = s2 * (1.f / D_MODEL) - mean * mean;
    float rstd = rsqrtf(var + LN_EPS);
    float4 g = reinterpret_cast<const float4*>(gam)[j];
    float4 b = reinterpret_cast<const float4*>(bet)[j];
    float4 o;
    o.x = (x.x - mean) * rstd * g.x + b.x;
    o.y = (x.y - mean) * rstd * g.y + b.y;
    o.z = (x.z - mean) * rstd * g.z + b.z;
    o.w = (x.w - mean) * rstd * g.w + b.w;
    reinterpret_cast<float4*>(out)[ro4] = o;
}

// ---------------- persistent GEMM, dynamic tiles, MIO-interleaved pipeline -------
// CTA tile 128x128, 128 threads (2x2 warps of 64x64), BK=64, 3-stage ring.
// cp.async split into 4 parts (one per ks, issued AFTER that ks's ldsm);
// cross-kt fragment preload: each kt ends wait_group(1)+bar+ldsm(next ks0).
// EPI==1: C = gelu(acc + bias) -> g_H            (K=768,  KT=12, 1536 tiles)
// EPI==2: split-K3, raw acc -> g_P/g_P2/g_P3     (Kc=1024, KT=16, 1152 tiles)
#define BK 64
#define LDT 72                        // padded smem row elems; 144B stride
#define TILE_B 18432                  // 128*72*2 per operand
#define STAGE_B 36864
#define NSTAGE 3
#define SMEM_GEMM (NSTAGE * STAGE_B + 16)

template <int EPI>
__global__ void __launch_bounds__(128, 2) gemm_kernel(const float* __restrict__ bias) {
    const __half* __restrict__ Ap = (EPI == 1) ? g_A : g_H;
    const __half* __restrict__ Bp = (EPI == 1) ? g_Wi : g_Wf;
    const int K  = (EPI == 1) ? D_MODEL : D_FF;
    const int NN = (EPI == 1) ? D_FF : D_MODEL;
    const int KT = (EPI == 1) ? 12 : 16;            // slabs per tile
    const int NT = (EPI == 1) ? 1536 : 1152;        // total tiles
    unsigned* ctr = (EPI == 1) ? &g_ctr1 : &g_ctr2;

    extern __shared__ char smem[];
    const uint32_t smem_u32 = (uint32_t)__cvta_generic_to_shared(smem);
    volatile unsigned* sm_next = (volatile unsigned*)(smem + NSTAGE * STAGE_B);

    const int tid = threadIdx.x;
    const int lane = tid & 31;
    const int warp = tid >> 5;
    const int wm = warp >> 1;
    const int wn = warp & 1;
    const int lrow = tid >> 3;        // 0..15
    const int lcol = tid & 7;         // 0..7

    __shared__ unsigned s_t0;
    if (tid == 0) s_t0 = atomicAdd(ctr, 1u);
    __syncthreads();
    unsigned t = s_t0;
    if (t >= (unsigned)NT) return;

    auto decode = [&](unsigned tt, int& mb, int& nb, int& kb) {
        if (EPI == 1) { nb = (tt % 24) * 128; mb = (tt / 24) * 128; kb = 0; }
        else          { nb = (tt % 6) * 128; mb = ((tt / 6) % 64) * 128; kb = (tt / 384) * 1024; }
    };

    int m_blk, n_blk, k_base;
    decode(t, m_blk, n_blk, k_base);

    const __half* pA = Ap + (size_t)(m_blk + lrow) * K + lcol * 8 + k_base;
    const __half* pB = Bp + (size_t)(n_blk + lrow) * K + lcol * 8 + k_base;

    const uint32_t sm_woff = (uint32_t)(lrow * 144 + lcol * 16);

    // one quarter (2x16 rows of A and B) of a BK=64 slab
    auto load_part = [&](int s, int koff, const __half* a, const __half* b, int part) {
        uint32_t base = smem_u32 + s * STAGE_B + sm_woff + (uint32_t)(part * 32 * 144);
        const __half* ga = a + (size_t)(part * 32) * K + koff;
        const __half* gb = b + (size_t)(part * 32) * K + koff;
        cp16(base,                       ga);
        cp16(base + TILE_B,              gb);
        cp16(base + 16 * 144,            ga + (size_t)16 * K);
        cp16(base + 16 * 144 + TILE_B,   gb + (size_t)16 * K);
    };

    const int a_row = wm * 64 + (lane & 15);
    const int a_k = (lane >> 4) * 8;
    const int b_row = wn * 64 + (lane & 7) + ((lane >> 4) & 1) * 8;
    const int b_k = ((lane >> 3) & 1) * 8;

    uint32_t aF[2][4][4], bF[2][4][4];
    auto ldsm_frags = [&](int buf, uint32_t base, int ks) {
        const int k0 = ks * 16;
        #pragma unroll
        for (int mt = 0; mt < 4; ++mt)
            ldsm4(aF[buf][mt], base + (uint32_t)((a_row + mt * 16) * LDT + k0 + a_k) * 2);
        #pragma unroll
        for (int np = 0; np < 4; ++np)
            ldsm4(bF[buf][np], base + TILE_B +
                                   (uint32_t)((b_row + np * 16) * LDT + k0 + b_k) * 2);
    };

    // preamble: slabs 0 and 1 of first tile; preload ks0 frags of slab 0
    #pragma unroll
    for (int p = 0; p < 4; ++p) load_part(0, 0, pA, pB, p);
    asm volatile("cp.async.commit_group;");
    #pragma unroll
    for (int p = 0; p < 4; ++p) load_part(1, BK, pA, pB, p);
    asm volatile("cp.async.commit_group;");
    asm volatile("cp.async.wait_group 1;");
    __syncthreads();
    ldsm_frags(0, smem_u32, 0);

    int cur_st = 0;
    for (;;) {
        if (tid == 0) sm_next[0] = atomicAdd(ctr, 1u);

        float acc[4][8][4];
        #pragma unroll
        for (int a = 0; a < 4; a++)
            #pragma unroll
            for (int b = 0; b < 8; b++)
                #pragma unroll
                for (int c = 0; c < 4; c++) acc[a][b][c] = 0.f;

        unsigned t_next = 0;
        bool has_next = false;
        int nm = 0, nn2 = 0, nk = 0;
        const __half *pAn = pA, *pBn = pB;

        for (int kt = 0; kt < KT; ++kt) {
            if (kt == KT - 2) {
                t_next = sm_next[0];
                has_next = t_next < (unsigned)NT;
                if (has_next) {
                    decode(t_next, nm, nn2, nk);
                    pAn = Ap + (size_t)(nm + lrow) * K + lcol * 8 + nk;
                    pBn = Bp + (size_t)(nn2 + lrow) * K + lcol * 8 + nk;
                }
            }

            const uint32_t base = smem_u32 + cur_st * STAGE_B;
            int p_st = cur_st + 2; if (p_st >= NSTAGE) p_st -= NSTAGE;
            const bool tail = (kt + 2 >= KT);
            const bool do_cp = !tail || has_next;
            const int koff = (tail ? (kt + 2 - KT) : (kt + 2)) * BK;
            const __half* qA = tail ? pAn : pA;
            const __half* qB = tail ? pBn : pB;

            #pragma unroll
            for (int ks = 0; ks < 4; ++ks) {
                const int cur = ks & 1;
                if (ks < 3) ldsm_frags(cur ^ 1, base, ks + 1);
                if (do_cp) load_part(p_st, koff, qA, qB, ks);
                if (ks == 3) asm volatile("cp.async.commit_group;");
                #pragma unroll
                for (int mt = 0; mt < 4; ++mt)
                    #pragma unroll
                    for (int nt = 0; nt < 8; ++nt) {
                        uint32_t b0 = bF[cur][nt >> 1][(nt & 1) * 2];
                        uint32_t b1 = bF[cur][nt >> 1][(nt & 1) * 2 + 1];
                        mma_f16(acc[mt][nt], aF[cur][mt], b0, b1);
                    }
            }

            // slab kt+1 guaranteed complete; preload its ks0 fragments
            asm volatile("cp.async.wait_group 1;");
            __syncthreads();
            int nxt_st = cur_st + 1; if (nxt_st >= NSTAGE) nxt_st -= NSTAGE;
            if (kt + 1 < KT || has_next)
                ldsm_frags(0, smem_u32 + nxt_st * STAGE_B, 0);
            cur_st = nxt_st;
        }

        // ---------------- epilogue ----------------
        float* Pout = g_P;
        if (EPI == 2) Pout = (k_base == 0) ? g_P : (k_base == 1024 ? g_P2 : g_P3);
        #pragma unroll
        for (int mt = 0; mt < 4; ++mt)
            #pragma unroll
            for (int nt = 0; nt < 8; ++nt) {
                int n = n_blk + wn * 64 + nt * 8 + (lane & 3) * 2;
                float b0 = 0.f, b1 = 0.f;
                if (EPI == 1) { b0 = bias[n]; b1 = bias[n + 1]; }
                #pragma unroll
                for (int h = 0; h < 2; ++h) {
                    int m = m_blk + wm * 64 + mt * 16 + (lane >> 2) + h * 8;
                    float x0 = acc[mt][nt][2 * h + 0] + b0;
                    float x1 = acc[mt][nt][2 * h + 1] + b1;
                    size_t o = (size_t)m * NN + n;
                    if (EPI == 1) {
                        __half2 hv = __floats2half2_rn(gelu_exact(x0), gelu_exact(x1));
                        *reinterpret_cast<__half2*>(&g_H[o]) = hv;
                    } else {
                        float2 v; v.x = x0; v.y = x1;
                        *reinterpret_cast<float2*>(&Pout[o]) = v;
                    }
                }
            }

        if (!has_next) break;
        t = t_next; m_blk = nm; n_blk = nn2; k_base = nk;
        pA = pAn; pB = pBn;
    }
}

// ---------------- launch ---------------------------------------------------------
extern "C" void kernel_launch(void* const* d_in, const int* in_sizes, int n_in,
                              void* d_out, int out_size) {
    (void)in_sizes; (void)n_in; (void)out_size;
    const float* hidden = (const float*)d_in[0];
    // d_in[1..6] = Wq,bq,Wk,bk,Wv,bv — dead (q/k/v overwritten by constants)
    const float* Wo   = (const float*)d_in[7];
    const float* bo   = (const float*)d_in[8];
    const float* ln1g = (const float*)d_in[9];
    const float* ln1b = (const float*)d_in[10];
    const float* Wi   = (const float*)d_in[11];
    const float* bi   = (const float*)d_in[12];
    const float* Wf   = (const float*)d_in[13];
    const float* bf_  = (const float*)d_in[14];
    const float* ln2g = (const float*)d_in[15];
    const float* ln2b = (const float*)d_in[16];
    float* out = (float*)d_out;

    cudaFuncSetAttribute(gemm_kernel<1>, cudaFuncAttributeMaxDynamicSharedMemorySize, SMEM_GEMM);
    cudaFuncSetAttribute(gemm_kernel<2>, cudaFuncAttributeMaxDynamicSharedMemorySize, SMEM_GEMM);

    rowsum_kernel<<<96, 256>>>(Wo, bo);
    prep_kernel<<<MROWS + CONV_BLOCKS, 192>>>(hidden, ln1g, ln1b, Wi, Wf);

    gemm_kernel<1><<<GRIDP, 128, SMEM_GEMM>>>(bi);
    gemm_kernel<2><<<GRIDP, 128, SMEM_GEMM>>>(bf_);

    ln2_kernel<<<MROWS, 192>>>(ln2g, ln2b, bf_, out);
}

// round 9
// speedup vs baseline: 3.7897x; 1.0160x over previous
#include <cuda_runtime.h>
#include <cuda_fp16.h>
#include <stdint.h>

#define D_MODEL 768
#define D_FF    3072
#define MROWS   8192   // B*S = 4*2048
#define LN_EPS  1e-12f
#define GRIDP   296    // persistent CTA count (2 per SM on 148-SM die)

// ---------------- scratch (__device__ globals; no runtime allocation) ----------
__device__ float   g_c[D_MODEL];
__device__ float   g_attn[(size_t)MROWS * D_MODEL];
__device__ __half  g_A[(size_t)MROWS * D_MODEL];
__device__ __half  g_Wi[(size_t)D_FF * D_MODEL];
__device__ __half  g_Wf[(size_t)D_MODEL * D_FF];
__device__ __half  g_H[(size_t)MROWS * D_FF];
__device__ __half  g_P[(size_t)MROWS * D_MODEL];
__device__ __half  g_P2[(size_t)MROWS * D_MODEL];
__device__ __half  g_P3[(size_t)MROWS * D_MODEL];
__device__ unsigned g_ctr1, g_ctr2;

// ---------------- helpers --------------------------------------------------------
__device__ __forceinline__ float gelu_exact(float x) {
    return 0.5f * x * (1.0f + erff(x * 0.7071067811865476f));
}

__device__ __forceinline__ void ldsm4(uint32_t (&r)[4], uint32_t addr) {
    asm volatile("ldmatrix.sync.aligned.m8n8.x4.shared.b16 {%0,%1,%2,%3}, [%4];"
                 : "=r"(r[0]), "=r"(r[1]), "=r"(r[2]), "=r"(r[3])
                 : "r"(addr));
}

__device__ __forceinline__ void mma_f16(float (&c)[4], const uint32_t (&a)[4],
                                        uint32_t b0, uint32_t b1) {
    asm volatile(
        "mma.sync.aligned.m16n8k16.row.col.f32.f16.f16.f32 "
        "{%0,%1,%2,%3},{%4,%5,%6,%7},{%8,%9},{%0,%1,%2,%3};"
        : "+f"(c[0]), "+f"(c[1]), "+f"(c[2]), "+f"(c[3])
        : "r"(a[0]), "r"(a[1]), "r"(a[2]), "r"(a[3]), "r"(b0), "r"(b1));
}

__device__ __forceinline__ void cp16(uint32_t saddr, const void* g) {
    asm volatile("cp.async.cg.shared.global [%0], [%1], 16;" ::"r"(saddr), "l"(g));
}

// block reduce for 192 threads (6 warps)
__device__ __forceinline__ void block_reduce2_192(float& s, float& s2) {
    __shared__ float red[2][6];
    #pragma unroll
    for (int o = 16; o; o >>= 1) {
        s  += __shfl_down_sync(0xffffffffu, s,  o);
        s2 += __shfl_down_sync(0xffffffffu, s2, o);
    }
    int lane = threadIdx.x & 31, w = threadIdx.x >> 5;
    if (lane == 0) { red[0][w] = s; red[1][w] = s2; }
    __syncthreads();
    if (w == 0) {
        s  = (lane < 6) ? red[0][lane] : 0.f;
        s2 = (lane < 6) ? red[1][lane] : 0.f;
        #pragma unroll
        for (int o = 4; o; o >>= 1) {
            s  += __shfl_down_sync(0xffffffffu, s,  o);
            s2 += __shfl_down_sync(0xffffffffu, s2, o);
        }
        if (lane == 0) { red[0][0] = s; red[1][0] = s2; }
    }
    __syncthreads();
    s = red[0][0];
    s2 = red[1][0];
}

// ---------------- small kernels --------------------------------------------------
// also resets the dynamic-scheduler counters each replay
__global__ void rowsum_kernel(const float* __restrict__ Wo, const float* __restrict__ bo) {
    if (blockIdx.x == 0 && threadIdx.x == 0) { g_ctr1 = 0; g_ctr2 = 0; }
    int gw = (blockIdx.x * blockDim.x + threadIdx.x) >> 5;
    int lane = threadIdx.x & 31;
    if (gw >= D_MODEL) return;
    const float* r = Wo + (size_t)gw * D_MODEL;
    float s = 0.f;
    for (int j = lane; j < D_MODEL; j += 32) s += r[j];
    #pragma unroll
    for (int o = 16; o; o >>= 1) s += __shfl_down_sync(0xffffffffu, s, o);
    if (lane == 0) g_c[gw] = 0.01f * s + bo[gw];
}

// merged: blocks [0,MROWS) do ln1 rows; the rest convert Wi/Wf to fp16
#define CONV_BLOCKS 6144   // 2*(D_FF*D_MODEL/4)/192
__global__ void prep_kernel(const float* __restrict__ hidden,
                            const float* __restrict__ gam, const float* __restrict__ bet,
                            const float* __restrict__ Wi, const float* __restrict__ Wf) {
    int bid = blockIdx.x;
    if (bid < MROWS) {
        int row = bid;
        int j = threadIdx.x;  // 0..191
        float4 x = reinterpret_cast<const float4*>(hidden + (size_t)row * D_MODEL)[j];
        float4 c = reinterpret_cast<const float4*>(g_c)[j];
        x.x += c.x; x.y += c.y; x.z += c.z; x.w += c.w;
        float s  = x.x + x.y + x.z + x.w;
        float s2 = x.x * x.x + x.y * x.y + x.z * x.z + x.w * x.w;
        block_reduce2_192(s, s2);
        float mean = s * (1.f / D_MODEL);
        float var = s2 * (1.f / D_MODEL) - mean * mean;
        float rstd = rsqrtf(var + LN_EPS);
        float4 g = reinterpret_cast<const float4*>(gam)[j];
        float4 b = reinterpret_cast<const float4*>(bet)[j];
        float4 a;
        a.x = (x.x - mean) * rstd * g.x + b.x;
        a.y = (x.y - mean) * rstd * g.y + b.y;
        a.z = (x.z - mean) * rstd * g.z + b.z;
        a.w = (x.w - mean) * rstd * g.w + b.w;
        reinterpret_cast<float4*>(g_attn + (size_t)row * D_MODEL)[j] = a;
        __half2 h0 = __floats2half2_rn(a.x, a.y);
        __half2 h1 = __floats2half2_rn(a.z, a.w);
        reinterpret_cast<uint2*>(g_A + (size_t)row * D_MODEL)[j] =
            make_uint2(*(uint32_t*)&h0, *(uint32_t*)&h1);
    } else {
        constexpr int n4 = D_FF * D_MODEL / 4;
        int i = (bid - MROWS) * 192 + threadIdx.x;
        const float* src;
        __half* Wh;
        int j;
        if (i < n4) { src = Wi; Wh = g_Wi; j = i; }
        else        { src = Wf; Wh = g_Wf; j = i - n4; }
        float4 v = reinterpret_cast<const float4*>(src)[j];
        __half2 h01 = __floats2half2_rn(v.x, v.y);
        __half2 h23 = __floats2half2_rn(v.z, v.w);
        reinterpret_cast<uint2*>(Wh)[j] =
            make_uint2(*(uint32_t*)&h01, *(uint32_t*)&h23);
    }
}

// out = LN(P0 + P1 + P2 + attn + bf); 192 threads, 4 cols each
__global__ void ln2_kernel(const float* __restrict__ gam, const float* __restrict__ bet,
                           const float* __restrict__ bf, float* __restrict__ out) {
    int row = blockIdx.x;
    int j = threadIdx.x;
    size_t ro = (size_t)row * D_MODEL + 4 * j;
    const __half2* p0 = reinterpret_cast<const __half2*>(g_P + ro);
    const __half2* p1 = reinterpret_cast<const __half2*>(g_P2 + ro);
    const __half2* p2 = reinterpret_cast<const __half2*>(g_P3 + ro);
    float2 a0 = __half22float2(p0[0]), a1 = __half22float2(p0[1]);
    float2 b0 = __half22float2(p1[0]), b1 = __half22float2(p1[1]);
    float2 c0 = __half22float2(p2[0]), c1 = __half22float2(p2[1]);
    float4 at = reinterpret_cast<const float4*>(g_attn + ro)[0];
    float4 bv = reinterpret_cast<const float4*>(bf)[j];
    float4 x;
    x.x = a0.x + b0.x + c0.x + at.x + bv.x;
    x.y = a0.y + b0.y + c0.y + at.y + bv.y;
    x.z = a1.x + b1.x + c1.x + at.z + bv.z;
    x.w = a1.y + b1.y + c1.y + at.w + bv.w;
    float s  = x.x + x.y + x.z + x.w;
    float s2 = x.x * x.x + x.y * x.y + x.z * x.z + x.w * x.w;
    block_reduce2_192(s, s2);
    float mean = s * (1.f / D_MODEL);
    float var = s2 * (1.f / D_MODEL) - mean * mean;
    float rstd = rsqrtf(var + LN_EPS);
    float4 g = reinterpret_cast<const float4*>(gam)[j];
    float4 b = reinterpret_cast<const float4*>(bet)[j];
    float4 o;
    o.x = (x.x - mean) * rstd * g.x + b.x;
    o.y = (x.y - mean) * rstd * g.y + b.y;
    o.z = (x.z - mean) * rstd * g.z + b.z;
    o.w = (x.w - mean) * rstd * g.w + b.w;
    reinterpret_cast<float4*>(out + ro)[0] = o;
}

// ---------------- persistent GEMM, dynamic tiles, MIO-interleaved pipeline -------
// CTA tile 128x128, 128 threads (2x2 warps of 64x64), BK=64, 3-stage ring.
// cp.async split into 4 parts, each issued BETWEEN the two mma half-bursts of a
// ks; cross-kt fragment preload after wait+bar.
// EPI==1: C = gelu(acc + bias) -> g_H            (K=768,  KT=12, 1536 tiles)
// EPI==2: split-K3, fp16 partials -> g_P/g_P2/g_P3 (Kc=1024, KT=16, 1152 tiles)
#define BK 64
#define LDT 72                        // padded smem row elems; 144B stride
#define TILE_B 18432                  // 128*72*2 per operand
#define STAGE_B 36864
#define NSTAGE 3
#define SMEM_GEMM (NSTAGE * STAGE_B + 16)

template <int EPI>
__global__ void __launch_bounds__(128, 2) gemm_kernel(const float* __restrict__ bias) {
    const __half* __restrict__ Ap = (EPI == 1) ? g_A : g_H;
    const __half* __restrict__ Bp = (EPI == 1) ? g_Wi : g_Wf;
    const int K  = (EPI == 1) ? D_MODEL : D_FF;
    const int NN = (EPI == 1) ? D_FF : D_MODEL;
    const int KT = (EPI == 1) ? 12 : 16;            // slabs per tile
    const int NT = (EPI == 1) ? 1536 : 1152;        // total tiles
    unsigned* ctr = (EPI == 1) ? &g_ctr1 : &g_ctr2;

    extern __shared__ char smem[];
    const uint32_t smem_u32 = (uint32_t)__cvta_generic_to_shared(smem);
    volatile unsigned* sm_next = (volatile unsigned*)(smem + NSTAGE * STAGE_B);

    const int tid = threadIdx.x;
    const int lane = tid & 31;
    const int warp = tid >> 5;
    const int wm = warp >> 1;
    const int wn = warp & 1;
    const int lrow = tid >> 3;        // 0..15
    const int lcol = tid & 7;         // 0..7

    __shared__ unsigned s_t0;
    if (tid == 0) s_t0 = atomicAdd(ctr, 1u);
    __syncthreads();
    unsigned t = s_t0;
    if (t >= (unsigned)NT) return;

    auto decode = [&](unsigned tt, int& mb, int& nb, int& kb) {
        if (EPI == 1) { nb = (tt % 24) * 128; mb = (tt / 24) * 128; kb = 0; }
        else          { nb = (tt % 6) * 128; mb = ((tt / 6) % 64) * 128; kb = (tt / 384) * 1024; }
    };

    int m_blk, n_blk, k_base;
    decode(t, m_blk, n_blk, k_base);

    const __half* pA = Ap + (size_t)(m_blk + lrow) * K + lcol * 8 + k_base;
    const __half* pB = Bp + (size_t)(n_blk + lrow) * K + lcol * 8 + k_base;

    const uint32_t sm_woff = (uint32_t)(lrow * 144 + lcol * 16);

    // one quarter (2x16 rows of A and B) of a BK=64 slab
    auto load_part = [&](int s, int koff, const __half* a, const __half* b, int part) {
        uint32_t base = smem_u32 + s * STAGE_B + sm_woff + (uint32_t)(part * 32 * 144);
        const __half* ga = a + (size_t)(part * 32) * K + koff;
        const __half* gb = b + (size_t)(part * 32) * K + koff;
        cp16(base,                       ga);
        cp16(base + TILE_B,              gb);
        cp16(base + 16 * 144,            ga + (size_t)16 * K);
        cp16(base + 16 * 144 + TILE_B,   gb + (size_t)16 * K);
    };

    const int a_row = wm * 64 + (lane & 15);
    const int a_k = (lane >> 4) * 8;
    const int b_row = wn * 64 + (lane & 7) + ((lane >> 4) & 1) * 8;
    const int b_k = ((lane >> 3) & 1) * 8;

    uint32_t aF[2][4][4], bF[2][4][4];
    auto ldsm_frags = [&](int buf, uint32_t base, int ks) {
        const int k0 = ks * 16;
        #pragma unroll
        for (int mt = 0; mt < 4; ++mt)
            ldsm4(aF[buf][mt], base + (uint32_t)((a_row + mt * 16) * LDT + k0 + a_k) * 2);
        #pragma unroll
        for (int np = 0; np < 4; ++np)
            ldsm4(bF[buf][np], base + TILE_B +
                                   (uint32_t)((b_row + np * 16) * LDT + k0 + b_k) * 2);
    };

    // preamble: slabs 0 and 1 of first tile; preload ks0 frags of slab 0
    #pragma unroll
    for (int p = 0; p < 4; ++p) load_part(0, 0, pA, pB, p);
    asm volatile("cp.async.commit_group;");
    #pragma unroll
    for (int p = 0; p < 4; ++p) load_part(1, BK, pA, pB, p);
    asm volatile("cp.async.commit_group;");
    asm volatile("cp.async.wait_group 1;");
    __syncthreads();
    ldsm_frags(0, smem_u32, 0);

    int cur_st = 0;
    for (;;) {
        if (tid == 0) sm_next[0] = atomicAdd(ctr, 1u);

        float acc[4][8][4];
        #pragma unroll
        for (int a = 0; a < 4; a++)
            #pragma unroll
            for (int b = 0; b < 8; b++)
                #pragma unroll
                for (int c = 0; c < 4; c++) acc[a][b][c] = 0.f;

        unsigned t_next = 0;
        bool has_next = false;
        int nm = 0, nn2 = 0, nk = 0;
        const __half *pAn = pA, *pBn = pB;

        for (int kt = 0; kt < KT; ++kt) {
            if (kt == KT - 2) {
                t_next = sm_next[0];
                has_next = t_next < (unsigned)NT;
                if (has_next) {
                    decode(t_next, nm, nn2, nk);
                    pAn = Ap + (size_t)(nm + lrow) * K + lcol * 8 + nk;
                    pBn = Bp + (size_t)(nn2 + lrow) * K + lcol * 8 + nk;
                }
            }

            const uint32_t base = smem_u32 + cur_st * STAGE_B;
            int p_st = cur_st + 2; if (p_st >= NSTAGE) p_st -= NSTAGE;
            const bool tail = (kt + 2 >= KT);
            const bool do_cp = !tail || has_next;
            const int koff = (tail ? (kt + 2 - KT) : (kt + 2)) * BK;
            const __half* qA = tail ? pAn : pA;
            const __half* qB = tail ? pBn : pB;

            #pragma unroll
            for (int ks = 0; ks < 4; ++ks) {
                const int cur = ks & 1;
                if (ks < 3) ldsm_frags(cur ^ 1, base, ks + 1);
                // first mma half-burst (mt 0..1)
                #pragma unroll
                for (int mt = 0; mt < 2; ++mt)
                    #pragma unroll
                    for (int nt = 0; nt < 8; ++nt) {
                        uint32_t b0 = bF[cur][nt >> 1][(nt & 1) * 2];
                        uint32_t b1 = bF[cur][nt >> 1][(nt & 1) * 2 + 1];
                        mma_f16(acc[mt][nt], aF[cur][mt], b0, b1);
                    }
                // cp.async for slab kt+2 overlaps with tensor-busy window
                if (do_cp) load_part(p_st, koff, qA, qB, ks);
                if (ks == 3) asm volatile("cp.async.commit_group;");
                // second mma half-burst (mt 2..3)
                #pragma unroll
                for (int mt = 2; mt < 4; ++mt)
                    #pragma unroll
                    for (int nt = 0; nt < 8; ++nt) {
                        uint32_t b0 = bF[cur][nt >> 1][(nt & 1) * 2];
                        uint32_t b1 = bF[cur][nt >> 1][(nt & 1) * 2 + 1];
                        mma_f16(acc[mt][nt], aF[cur][mt], b0, b1);
                    }
            }

            // slab kt+1 guaranteed complete; preload its ks0 fragments
            asm volatile("cp.async.wait_group 1;");
            __syncthreads();
            int nxt_st = cur_st + 1; if (nxt_st >= NSTAGE) nxt_st -= NSTAGE;
            if (kt + 1 < KT || has_next)
                ldsm_frags(0, smem_u32 + nxt_st * STAGE_B, 0);
            cur_st = nxt_st;
        }

        // ---------------- epilogue ----------------
        __half* Pout = g_P;
        if (EPI == 2) Pout = (k_base == 0) ? g_P : (k_base == 1024 ? g_P2 : g_P3);
        #pragma unroll
        for (int mt = 0; mt < 4; ++mt)
            #pragma unroll
            for (int nt = 0; nt < 8; ++nt) {
                int n = n_blk + wn * 64 + nt * 8 + (lane & 3) * 2;
                float b0 = 0.f, b1 = 0.f;
                if (EPI == 1) { b0 = bias[n]; b1 = bias[n + 1]; }
                #pragma unroll
                for (int h = 0; h < 2; ++h) {
                    int m = m_blk + wm * 64 + mt * 16 + (lane >> 2) + h * 8;
                    float x0 = acc[mt][nt][2 * h + 0] + b0;
                    float x1 = acc[mt][nt][2 * h + 1] + b1;
                    size_t o = (size_t)m * NN + n;
                    if (EPI == 1) {
                        __half2 hv = __floats2half2_rn(gelu_exact(x0), gelu_exact(x1));
                        *reinterpret_cast<__half2*>(&g_H[o]) = hv;
                    } else {
                        __half2 hv = __floats2half2_rn(x0, x1);
                        *reinterpret_cast<__half2*>(&Pout[o]) = hv;
                    }
                }
            }

        if (!has_next) break;
        t = t_next; m_blk = nm; n_blk = nn2; k_base = nk;
        pA = pAn; pB = pBn;
    }
}

// ---------------- launch ---------------------------------------------------------
extern "C" void kernel_launch(void* const* d_in, const int* in_sizes, int n_in,
                              void* d_out, int out_size) {
    (void)in_sizes; (void)n_in; (void)out_size;
    const float* hidden = (const float*)d_in[0];
    // d_in[1..6] = Wq,bq,Wk,bk,Wv,bv — dead (q/k/v overwritten by constants)
    const float* Wo   = (const float*)d_in[7];
    const float* bo   = (const float*)d_in[8];
    const float* ln1g = (const float*)d_in[9];
    const float* ln1b = (const float*)d_in[10];
    const float* Wi   = (const float*)d_in[11];
    const float* bi   = (const float*)d_in[12];
    const float* Wf   = (const float*)d_in[13];
    const float* bf_  = (const float*)d_in[14];
    const float* ln2g = (const float*)d_in[15];
    const float* ln2b = (const float*)d_in[16];
    float* out = (float*)d_out;

    cudaFuncSetAttribute(gemm_kernel<1>, cudaFuncAttributeMaxDynamicSharedMemorySize, SMEM_GEMM);
    cudaFuncSetAttribute(gemm_kernel<2>, cudaFuncAttributeMaxDynamicSharedMemorySize, SMEM_GEMM);

    rowsum_kernel<<<96, 256>>>(Wo, bo);
    prep_kernel<<<MROWS + CONV_BLOCKS, 192>>>(hidden, ln1g, ln1b, Wi, Wf);

    gemm_kernel<1><<<GRIDP, 128, SMEM_GEMM>>>(bi);
    gemm_kernel<2><<<GRIDP, 128, SMEM_GEMM>>>(bf_);

    ln2_kernel<<<MROWS, 192>>>(ln2g, ln2b, bf_, out);
}

// round 10
// speedup vs baseline: 3.8164x; 1.0071x over previous
#include <cuda_runtime.h>
#include <cuda_fp16.h>
#include <stdint.h>

#define D_MODEL 768
#define D_FF    3072
#define MROWS   8192   // B*S = 4*2048
#define LN_EPS  1e-12f
#define GRIDP   296    // persistent CTA count (2 per SM on 148-SM die)

// ---------------- scratch (__device__ globals; no runtime allocation) ----------
__device__ float   g_c[D_MODEL];
__device__ __half  g_A[(size_t)MROWS * D_MODEL];    // LN1 output (also ln2 residual)
__device__ __half  g_Wi[(size_t)D_FF * D_MODEL];
__device__ __half  g_Wf[(size_t)D_MODEL * D_FF];
__device__ __half  g_H[(size_t)MROWS * D_FF];
__device__ __half  g_P[(size_t)MROWS * D_MODEL];
__device__ __half  g_P2[(size_t)MROWS * D_MODEL];
__device__ __half  g_P3[(size_t)MROWS * D_MODEL];
__device__ unsigned g_ctr1, g_ctr2;

// ---------------- helpers --------------------------------------------------------
__device__ __forceinline__ float gelu_exact(float x) {
    return 0.5f * x * (1.0f + erff(x * 0.7071067811865476f));
}

__device__ __forceinline__ void ldsm4(uint32_t (&r)[4], uint32_t addr) {
    asm volatile("ldmatrix.sync.aligned.m8n8.x4.shared.b16 {%0,%1,%2,%3}, [%4];"
                 : "=r"(r[0]), "=r"(r[1]), "=r"(r[2]), "=r"(r[3])
                 : "r"(addr));
}

__device__ __forceinline__ void mma_f16(float (&c)[4], const uint32_t (&a)[4],
                                        uint32_t b0, uint32_t b1) {
    asm volatile(
        "mma.sync.aligned.m16n8k16.row.col.f32.f16.f16.f32 "
        "{%0,%1,%2,%3},{%4,%5,%6,%7},{%8,%9},{%0,%1,%2,%3};"
        : "+f"(c[0]), "+f"(c[1]), "+f"(c[2]), "+f"(c[3])
        : "r"(a[0]), "r"(a[1]), "r"(a[2]), "r"(a[3]), "r"(b0), "r"(b1));
}

__device__ __forceinline__ void cp16(uint32_t saddr, const void* g) {
    asm volatile("cp.async.cg.shared.global [%0], [%1], 16;" ::"r"(saddr), "l"(g));
}

// block reduce for 192 threads (6 warps)
__device__ __forceinline__ void block_reduce2_192(float& s, float& s2) {
    __shared__ float red[2][6];
    #pragma unroll
    for (int o = 16; o; o >>= 1) {
        s  += __shfl_down_sync(0xffffffffu, s,  o);
        s2 += __shfl_down_sync(0xffffffffu, s2, o);
    }
    int lane = threadIdx.x & 31, w = threadIdx.x >> 5;
    if (lane == 0) { red[0][w] = s; red[1][w] = s2; }
    __syncthreads();
    if (w == 0) {
        s  = (lane < 6) ? red[0][lane] : 0.f;
        s2 = (lane < 6) ? red[1][lane] : 0.f;
        #pragma unroll
        for (int o = 4; o; o >>= 1) {
            s  += __shfl_down_sync(0xffffffffu, s,  o);
            s2 += __shfl_down_sync(0xffffffffu, s2, o);
        }
        if (lane == 0) { red[0][0] = s; red[1][0] = s2; }
    }
    __syncthreads();
    s = red[0][0];
    s2 = red[1][0];
}

// ---------------- small kernels --------------------------------------------------
// also resets the dynamic-scheduler counters each replay
__global__ void rowsum_kernel(const float* __restrict__ Wo, const float* __restrict__ bo) {
    if (blockIdx.x == 0 && threadIdx.x == 0) { g_ctr1 = 0; g_ctr2 = 0; }
    int gw = (blockIdx.x * blockDim.x + threadIdx.x) >> 5;
    int lane = threadIdx.x & 31;
    if (gw >= D_MODEL) return;
    const float* r = Wo + (size_t)gw * D_MODEL;
    float s = 0.f;
    for (int j = lane; j < D_MODEL; j += 32) s += r[j];
    #pragma unroll
    for (int o = 16; o; o >>= 1) s += __shfl_down_sync(0xffffffffu, s, o);
    if (lane == 0) g_c[gw] = 0.01f * s + bo[gw];
}

// merged: blocks [0,MROWS) do ln1 rows; the rest convert Wi/Wf to fp16
#define CONV_BLOCKS 6144   // 2*(D_FF*D_MODEL/4)/192
__global__ void prep_kernel(const float* __restrict__ hidden,
                            const float* __restrict__ gam, const float* __restrict__ bet,
                            const float* __restrict__ Wi, const float* __restrict__ Wf) {
    int bid = blockIdx.x;
    if (bid < MROWS) {
        int row = bid;
        int j = threadIdx.x;  // 0..191
        float4 x = reinterpret_cast<const float4*>(hidden + (size_t)row * D_MODEL)[j];
        float4 c = reinterpret_cast<const float4*>(g_c)[j];
        x.x += c.x; x.y += c.y; x.z += c.z; x.w += c.w;
        float s  = x.x + x.y + x.z + x.w;
        float s2 = x.x * x.x + x.y * x.y + x.z * x.z + x.w * x.w;
        block_reduce2_192(s, s2);
        float mean = s * (1.f / D_MODEL);
        float var = s2 * (1.f / D_MODEL) - mean * mean;
        float rstd = rsqrtf(var + LN_EPS);
        float4 g = reinterpret_cast<const float4*>(gam)[j];
        float4 b = reinterpret_cast<const float4*>(bet)[j];
        float4 a;
        a.x = (x.x - mean) * rstd * g.x + b.x;
        a.y = (x.y - mean) * rstd * g.y + b.y;
        a.z = (x.z - mean) * rstd * g.z + b.z;
        a.w = (x.w - mean) * rstd * g.w + b.w;
        __half2 h0 = __floats2half2_rn(a.x, a.y);
        __half2 h1 = __floats2half2_rn(a.z, a.w);
        reinterpret_cast<uint2*>(g_A + (size_t)row * D_MODEL)[j] =
            make_uint2(*(uint32_t*)&h0, *(uint32_t*)&h1);
    } else {
        constexpr int n4 = D_FF * D_MODEL / 4;
        int i = (bid - MROWS) * 192 + threadIdx.x;
        const float* src;
        __half* Wh;
        int j;
        if (i < n4) { src = Wi; Wh = g_Wi; j = i; }
        else        { src = Wf; Wh = g_Wf; j = i - n4; }
        float4 v = reinterpret_cast<const float4*>(src)[j];
        __half2 h01 = __floats2half2_rn(v.x, v.y);
        __half2 h23 = __floats2half2_rn(v.z, v.w);
        reinterpret_cast<uint2*>(Wh)[j] =
            make_uint2(*(uint32_t*)&h01, *(uint32_t*)&h23);
    }
}

// out = LN(P0 + P1 + P2 + A + bf); 192 threads, 4 cols each, all-fp16 inputs
__global__ void ln2_kernel(const float* __restrict__ gam, const float* __restrict__ bet,
                           const float* __restrict__ bf, float* __restrict__ out) {
    int row = blockIdx.x;
    int j = threadIdx.x;
    size_t ro = (size_t)row * D_MODEL + 4 * j;
    const __half2* p0 = reinterpret_cast<const __half2*>(g_P + ro);
    const __half2* p1 = reinterpret_cast<const __half2*>(g_P2 + ro);
    const __half2* p2 = reinterpret_cast<const __half2*>(g_P3 + ro);
    const __half2* pa = reinterpret_cast<const __half2*>(g_A + ro);
    float2 a0 = __half22float2(p0[0]), a1 = __half22float2(p0[1]);
    float2 b0 = __half22float2(p1[0]), b1 = __half22float2(p1[1]);
    float2 c0 = __half22float2(p2[0]), c1 = __half22float2(p2[1]);
    float2 t0 = __half22float2(pa[0]), t1 = __half22float2(pa[1]);
    float4 bv = reinterpret_cast<const float4*>(bf)[j];
    float4 x;
    x.x = a0.x + b0.x + c0.x + t0.x + bv.x;
    x.y = a0.y + b0.y + c0.y + t0.y + bv.y;
    x.z = a1.x + b1.x + c1.x + t1.x + bv.z;
    x.w = a1.y + b1.y + c1.y + t1.y + bv.w;
    float s  = x.x + x.y + x.z + x.w;
    float s2 = x.x * x.x + x.y * x.y + x.z * x.z + x.w * x.w;
    block_reduce2_192(s, s2);
    float mean = s * (1.f / D_MODEL);
    float var = s2 * (1.f / D_MODEL) - mean * mean;
    float rstd = rsqrtf(var + LN_EPS);
    float4 g = reinterpret_cast<const float4*>(gam)[j];
    float4 b = reinterpret_cast<const float4*>(bet)[j];
    float4 o;
    o.x = (x.x - mean) * rstd * g.x + b.x;
    o.y = (x.y - mean) * rstd * g.y + b.y;
    o.z = (x.z - mean) * rstd * g.z + b.z;
    o.w = (x.w - mean) * rstd * g.w + b.w;
    reinterpret_cast<float4*>(out + ro)[0] = o;
}

// ---------------- persistent GEMM, dynamic tiles, MIO-interleaved pipeline -------
// CTA tile 128x128, 128 threads (2x2 warps of 64x64), BK=64, 3-stage ring.
// cp.async split into 4 parts issued between mma half-bursts; cross-kt fragment
// preload after wait+bar; co-resident CTA pair de-phased via nanosleep.
// EPI==1: C = gelu(acc + bias) -> g_H              (K=768,  KT=12, 1536 tiles)
// EPI==2: split-K3, fp16 partials -> g_P/g_P2/g_P3 (Kc=1024, KT=16, 1152 tiles)
#define BK 64
#define LDT 72                        // padded smem row elems; 144B stride
#define TILE_B 18432                  // 128*72*2 per operand
#define STAGE_B 36864
#define NSTAGE 3
#define SMEM_GEMM (NSTAGE * STAGE_B + 16)

template <int EPI>
__global__ void __launch_bounds__(128, 2) gemm_kernel(const float* __restrict__ bias) {
    const __half* __restrict__ Ap = (EPI == 1) ? g_A : g_H;
    const __half* __restrict__ Bp = (EPI == 1) ? g_Wi : g_Wf;
    const int K  = (EPI == 1) ? D_MODEL : D_FF;
    const int NN = (EPI == 1) ? D_FF : D_MODEL;
    const int KT = (EPI == 1) ? 12 : 16;            // slabs per tile
    const int NT = (EPI == 1) ? 1536 : 1152;        // total tiles
    unsigned* ctr = (EPI == 1) ? &g_ctr1 : &g_ctr2;

    extern __shared__ char smem[];
    const uint32_t smem_u32 = (uint32_t)__cvta_generic_to_shared(smem);
    volatile unsigned* sm_next = (volatile unsigned*)(smem + NSTAGE * STAGE_B);

    const int tid = threadIdx.x;
    const int lane = tid & 31;
    const int warp = tid >> 5;
    const int wm = warp >> 1;
    const int wn = warp & 1;
    const int lrow = tid >> 3;        // 0..15
    const int lcol = tid & 7;         // 0..7

    // de-phase the second co-resident CTA on each SM (bid and bid+148 share an SM)
    __shared__ unsigned s_t0;
    if (tid == 0) {
        if (blockIdx.x >= 148) __nanosleep(1000);
        s_t0 = atomicAdd(ctr, 1u);
    }
    __syncthreads();
    unsigned t = s_t0;
    if (t >= (unsigned)NT) return;

    auto decode = [&](unsigned tt, int& mb, int& nb, int& kb) {
        if (EPI == 1) { nb = (tt % 24) * 128; mb = (tt / 24) * 128; kb = 0; }
        else          { nb = (tt % 6) * 128; mb = ((tt / 6) % 64) * 128; kb = (tt / 384) * 1024; }
    };

    int m_blk, n_blk, k_base;
    decode(t, m_blk, n_blk, k_base);

    const __half* pA = Ap + (size_t)(m_blk + lrow) * K + lcol * 8 + k_base;
    const __half* pB = Bp + (size_t)(n_blk + lrow) * K + lcol * 8 + k_base;

    const uint32_t sm_woff = (uint32_t)(lrow * 144 + lcol * 16);

    // one quarter (2x16 rows of A and B) of a BK=64 slab
    auto load_part = [&](int s, int koff, const __half* a, const __half* b, int part) {
        uint32_t base = smem_u32 + s * STAGE_B + sm_woff + (uint32_t)(part * 32 * 144);
        const __half* ga = a + (size_t)(part * 32) * K + koff;
        const __half* gb = b + (size_t)(part * 32) * K + koff;
        cp16(base,                       ga);
        cp16(base + TILE_B,              gb);
        cp16(base + 16 * 144,            ga + (size_t)16 * K);
        cp16(base + 16 * 144 + TILE_B,   gb + (size_t)16 * K);
    };

    const int a_row = wm * 64 + (lane & 15);
    const int a_k = (lane >> 4) * 8;
    const int b_row = wn * 64 + (lane & 7) + ((lane >> 4) & 1) * 8;
    const int b_k = ((lane >> 3) & 1) * 8;

    uint32_t aF[2][4][4], bF[2][4][4];
    auto ldsm_frags = [&](int buf, uint32_t base, int ks) {
        const int k0 = ks * 16;
        #pragma unroll
        for (int mt = 0; mt < 4; ++mt)
            ldsm4(aF[buf][mt], base + (uint32_t)((a_row + mt * 16) * LDT + k0 + a_k) * 2);
        #pragma unroll
        for (int np = 0; np < 4; ++np)
            ldsm4(bF[buf][np], base + TILE_B +
                                   (uint32_t)((b_row + np * 16) * LDT + k0 + b_k) * 2);
    };

    // preamble: slabs 0 and 1 of first tile; preload ks0 frags of slab 0
    #pragma unroll
    for (int p = 0; p < 4; ++p) load_part(0, 0, pA, pB, p);
    asm volatile("cp.async.commit_group;");
    #pragma unroll
    for (int p = 0; p < 4; ++p) load_part(1, BK, pA, pB, p);
    asm volatile("cp.async.commit_group;");
    asm volatile("cp.async.wait_group 1;");
    __syncthreads();
    ldsm_frags(0, smem_u32, 0);

    int cur_st = 0;
    for (;;) {
        if (tid == 0) sm_next[0] = atomicAdd(ctr, 1u);

        float acc[4][8][4];
        #pragma unroll
        for (int a = 0; a < 4; a++)
            #pragma unroll
            for (int b = 0; b < 8; b++)
                #pragma unroll
                for (int c = 0; c < 4; c++) acc[a][b][c] = 0.f;

        unsigned t_next = 0;
        bool has_next = false;
        int nm = 0, nn2 = 0, nk = 0;
        const __half *pAn = pA, *pBn = pB;

        for (int kt = 0; kt < KT; ++kt) {
            if (kt == KT - 2) {
                t_next = sm_next[0];
                has_next = t_next < (unsigned)NT;
                if (has_next) {
                    decode(t_next, nm, nn2, nk);
                    pAn = Ap + (size_t)(nm + lrow) * K + lcol * 8 + nk;
                    pBn = Bp + (size_t)(nn2 + lrow) * K + lcol * 8 + nk;
                }
            }

            const uint32_t base = smem_u32 + cur_st * STAGE_B;
            int p_st = cur_st + 2; if (p_st >= NSTAGE) p_st -= NSTAGE;
            const bool tail = (kt + 2 >= KT);
            const bool do_cp = !tail || has_next;
            const int koff = (tail ? (kt + 2 - KT) : (kt + 2)) * BK;
            const __half* qA = tail ? pAn : pA;
            const __half* qB = tail ? pBn : pB;

            #pragma unroll
            for (int ks = 0; ks < 4; ++ks) {
                const int cur = ks & 1;
                if (ks < 3) ldsm_frags(cur ^ 1, base, ks + 1);
                // first mma half-burst (mt 0..1)
                #pragma unroll
                for (int mt = 0; mt < 2; ++mt)
                    #pragma unroll
                    for (int nt = 0; nt < 8; ++nt) {
                        uint32_t b0 = bF[cur][nt >> 1][(nt & 1) * 2];
                        uint32_t b1 = bF[cur][nt >> 1][(nt & 1) * 2 + 1];
                        mma_f16(acc[mt][nt], aF[cur][mt], b0, b1);
                    }
                // cp.async for slab kt+2 overlaps with tensor-busy window
                if (do_cp) load_part(p_st, koff, qA, qB, ks);
                if (ks == 3) asm volatile("cp.async.commit_group;");
                // second mma half-burst (mt 2..3)
                #pragma unroll
                for (int mt = 2; mt < 4; ++mt)
                    #pragma unroll
                    for (int nt = 0; nt < 8; ++nt) {
                        uint32_t b0 = bF[cur][nt >> 1][(nt & 1) * 2];
                        uint32_t b1 = bF[cur][nt >> 1][(nt & 1) * 2 + 1];
                        mma_f16(acc[mt][nt], aF[cur][mt], b0, b1);
                    }
            }

            // slab kt+1 guaranteed complete; preload its ks0 fragments
            asm volatile("cp.async.wait_group 1;");
            __syncthreads();
            int nxt_st = cur_st + 1; if (nxt_st >= NSTAGE) nxt_st -= NSTAGE;
            if (kt + 1 < KT || has_next)
                ldsm_frags(0, smem_u32 + nxt_st * STAGE_B, 0);
            cur_st = nxt_st;
        }

        // ---------------- epilogue ----------------
        __half* Pout = g_P;
        if (EPI == 2) Pout = (k_base == 0) ? g_P : (k_base == 1024 ? g_P2 : g_P3);
        #pragma unroll
        for (int mt = 0; mt < 4; ++mt)
            #pragma unroll
            for (int nt = 0; nt < 8; ++nt) {
                int n = n_blk + wn * 64 + nt * 8 + (lane & 3) * 2;
                float b0 = 0.f, b1 = 0.f;
                if (EPI == 1) { b0 = bias[n]; b1 = bias[n + 1]; }
                #pragma unroll
                for (int h = 0; h < 2; ++h) {
                    int m = m_blk + wm * 64 + mt * 16 + (lane >> 2) + h * 8;
                    float x0 = acc[mt][nt][2 * h + 0] + b0;
                    float x1 = acc[mt][nt][2 * h + 1] + b1;
                    size_t o = (size_t)m * NN + n;
                    if (EPI == 1) {
                        __half2 hv = __floats2half2_rn(gelu_exact(x0), gelu_exact(x1));
                        *reinterpret_cast<__half2*>(&g_H[o]) = hv;
                    } else {
                        __half2 hv = __floats2half2_rn(x0, x1);
                        *reinterpret_cast<__half2*>(&Pout[o]) = hv;
                    }
                }
            }

        if (!has_next) break;
        t = t_next; m_blk = nm; n_blk = nn2; k_base = nk;
        pA = pAn; pB = pBn;
    }
}

// ---------------- launch ---------------------------------------------------------
extern "C" void kernel_launch(void* const* d_in, const int* in_sizes, int n_in,
                              void* d_out, int out_size) {
    (void)in_sizes; (void)n_in; (void)out_size;
    const float* hidden = (const float*)d_in[0];
    // d_in[1..6] = Wq,bq,Wk,bk,Wv,bv — dead (q/k/v overwritten by constants)
    const float* Wo   = (const float*)d_in[7];
    const float* bo   = (const float*)d_in[8];
    const float* ln1g = (const float*)d_in[9];
    const float* ln1b = (const float*)d_in[10];
    const float* Wi   = (const float*)d_in[11];
    const float* bi   = (const float*)d_in[12];
    const float* Wf   = (const float*)d_in[13];
    const float* bf_  = (const float*)d_in[14];
    const float* ln2g = (const float*)d_in[15];
    const float* ln2b = (const float*)d_in[16];
    float* out = (float*)d_out;

    cudaFuncSetAttribute(gemm_kernel<1>, cudaFuncAttributeMaxDynamicSharedMemorySize, SMEM_GEMM);
    cudaFuncSetAttribute(gemm_kernel<2>, cudaFuncAttributeMaxDynamicSharedMemorySize, SMEM_GEMM);

    rowsum_kernel<<<96, 256>>>(Wo, bo);
    prep_kernel<<<MROWS + CONV_BLOCKS, 192>>>(hidden, ln1g, ln1b, Wi, Wf);

    gemm_kernel<1><<<GRIDP, 128, SMEM_GEMM>>>(bi);
    gemm_kernel<2><<<GRIDP, 128, SMEM_GEMM>>>(bf_);

    ln2_kernel<<<MROWS, 192>>>(ln2g, ln2b, bf_, out);
}

// round 11
// speedup vs baseline: 3.8210x; 1.0012x over previous
#include <cuda_runtime.h>
#include <cuda_fp16.h>
#include <stdint.h>

#define D_MODEL 768
#define D_FF    3072
#define MROWS   8192   // B*S = 4*2048
#define LN_EPS  1e-12f
#define GRIDP   296    // persistent CTA count (2 per SM on 148-SM die)

// ---------------- scratch (__device__ globals; no runtime allocation) ----------
__device__ float   g_c[D_MODEL];
__device__ __half  g_A[(size_t)MROWS * D_MODEL];    // LN1 output (also ln2 residual)
__device__ __half  g_Wi[(size_t)D_FF * D_MODEL];
__device__ __half  g_Wf[(size_t)D_MODEL * D_FF];
__device__ __half  g_H[(size_t)MROWS * D_FF];
__device__ __half  g_P[(size_t)MROWS * D_MODEL];
__device__ __half  g_P2[(size_t)MROWS * D_MODEL];
__device__ __half  g_P3[(size_t)MROWS * D_MODEL];
__device__ unsigned g_ctr1, g_ctr2;

// ---------------- helpers --------------------------------------------------------
__device__ __forceinline__ float gelu_exact(float x) {
    return 0.5f * x * (1.0f + erff(x * 0.7071067811865476f));
}

__device__ __forceinline__ void ldsm4(uint32_t (&r)[4], uint32_t addr) {
    asm volatile("ldmatrix.sync.aligned.m8n8.x4.shared.b16 {%0,%1,%2,%3}, [%4];"
                 : "=r"(r[0]), "=r"(r[1]), "=r"(r[2]), "=r"(r[3])
                 : "r"(addr));
}

__device__ __forceinline__ void mma_f16(float (&c)[4], const uint32_t (&a)[4],
                                        uint32_t b0, uint32_t b1) {
    asm volatile(
        "mma.sync.aligned.m16n8k16.row.col.f32.f16.f16.f32 "
        "{%0,%1,%2,%3},{%4,%5,%6,%7},{%8,%9},{%0,%1,%2,%3};"
        : "+f"(c[0]), "+f"(c[1]), "+f"(c[2]), "+f"(c[3])
        : "r"(a[0]), "r"(a[1]), "r"(a[2]), "r"(a[3]), "r"(b0), "r"(b1));
}

__device__ __forceinline__ void cp16(uint32_t saddr, const void* g) {
    asm volatile("cp.async.cg.shared.global [%0], [%1], 16;" ::"r"(saddr), "l"(g));
}

// warp butterfly reduce (all lanes get result)
__device__ __forceinline__ void warp_reduce2(float& s, float& s2) {
    #pragma unroll
    for (int o = 16; o; o >>= 1) {
        s  += __shfl_xor_sync(0xffffffffu, s,  o);
        s2 += __shfl_xor_sync(0xffffffffu, s2, o);
    }
}

// ---------------- small kernels --------------------------------------------------
// also resets the dynamic-scheduler counters each replay
__global__ void rowsum_kernel(const float* __restrict__ Wo, const float* __restrict__ bo) {
    if (blockIdx.x == 0 && threadIdx.x == 0) { g_ctr1 = 0; g_ctr2 = 0; }
    int gw = (blockIdx.x * blockDim.x + threadIdx.x) >> 5;
    int lane = threadIdx.x & 31;
    if (gw >= D_MODEL) return;
    const float* r = Wo + (size_t)gw * D_MODEL;
    float s = 0.f;
    for (int j = lane; j < D_MODEL; j += 32) s += r[j];
    #pragma unroll
    for (int o = 16; o; o >>= 1) s += __shfl_down_sync(0xffffffffu, s, o);
    if (lane == 0) g_c[gw] = 0.01f * s + bo[gw];
}

// merged: blocks [0,1024) = ln1 (warp per row, 8 rows/block);
//         blocks [1024, 1024+4608) = weight conversion
#define LN1_BLOCKS  1024
#define CONV_BLOCKS 4608   // 2*(D_FF*D_MODEL/4)/256
__global__ void __launch_bounds__(256) prep_kernel(
        const float* __restrict__ hidden,
        const float* __restrict__ gam, const float* __restrict__ bet,
        const float* __restrict__ Wi, const float* __restrict__ Wf) {
    int bid = blockIdx.x;
    if (bid < LN1_BLOCKS) {
        int warp = threadIdx.x >> 5, lane = threadIdx.x & 31;
        int row = bid * 8 + warp;
        const float4* xr = reinterpret_cast<const float4*>(hidden + (size_t)row * D_MODEL);
        const float4* cr = reinterpret_cast<const float4*>(g_c);
        float4 v[6];
        float s = 0.f, s2 = 0.f;
        #pragma unroll
        for (int i = 0; i < 6; i++) {
            float4 x = xr[lane + 32 * i];
            float4 c = cr[lane + 32 * i];
            x.x += c.x; x.y += c.y; x.z += c.z; x.w += c.w;
            v[i] = x;
            s  += x.x + x.y + x.z + x.w;
            s2 += x.x * x.x + x.y * x.y + x.z * x.z + x.w * x.w;
        }
        warp_reduce2(s, s2);
        float mean = s * (1.f / D_MODEL);
        float var = s2 * (1.f / D_MODEL) - mean * mean;
        float rstd = rsqrtf(var + LN_EPS);
        uint2* outp = reinterpret_cast<uint2*>(g_A + (size_t)row * D_MODEL);
        const float4* gr = reinterpret_cast<const float4*>(gam);
        const float4* br = reinterpret_cast<const float4*>(bet);
        #pragma unroll
        for (int i = 0; i < 6; i++) {
            float4 g = gr[lane + 32 * i];
            float4 b = br[lane + 32 * i];
            float4 a;
            a.x = (v[i].x - mean) * rstd * g.x + b.x;
            a.y = (v[i].y - mean) * rstd * g.y + b.y;
            a.z = (v[i].z - mean) * rstd * g.z + b.z;
            a.w = (v[i].w - mean) * rstd * g.w + b.w;
            __half2 h0 = __floats2half2_rn(a.x, a.y);
            __half2 h1 = __floats2half2_rn(a.z, a.w);
            outp[lane + 32 * i] = make_uint2(*(uint32_t*)&h0, *(uint32_t*)&h1);
        }
    } else {
        constexpr int n4 = D_FF * D_MODEL / 4;
        int i = (bid - LN1_BLOCKS) * 256 + threadIdx.x;
        const float* src;
        __half* Wh;
        int j;
        if (i < n4) { src = Wi; Wh = g_Wi; j = i; }
        else        { src = Wf; Wh = g_Wf; j = i - n4; }
        float4 v = reinterpret_cast<const float4*>(src)[j];
        __half2 h01 = __floats2half2_rn(v.x, v.y);
        __half2 h23 = __floats2half2_rn(v.z, v.w);
        reinterpret_cast<uint2*>(Wh)[j] =
            make_uint2(*(uint32_t*)&h01, *(uint32_t*)&h23);
    }
}

// out = LN(P0 + P1 + P2 + A + bf); warp per row, 8 rows/block
__global__ void __launch_bounds__(256) ln2_kernel(
        const float* __restrict__ gam, const float* __restrict__ bet,
        const float* __restrict__ bf, float* __restrict__ out) {
    int warp = threadIdx.x >> 5, lane = threadIdx.x & 31;
    int row = blockIdx.x * 8 + warp;
    size_t rbase = (size_t)row * (D_MODEL / 4);
    const uint2* p0 = reinterpret_cast<const uint2*>(g_P)  + rbase;
    const uint2* p1 = reinterpret_cast<const uint2*>(g_P2) + rbase;
    const uint2* p2 = reinterpret_cast<const uint2*>(g_P3) + rbase;
    const uint2* pa = reinterpret_cast<const uint2*>(g_A)  + rbase;
    const float4* bfr = reinterpret_cast<const float4*>(bf);
    float4 v[6];
    float s = 0.f, s2 = 0.f;
    #pragma unroll
    for (int i = 0; i < 6; i++) {
        int idx = lane + 32 * i;
        uint2 u0 = p0[idx], u1 = p1[idx], u2 = p2[idx], ua = pa[idx];
        float2 a0 = __half22float2(*(__half2*)&u0.x), a1 = __half22float2(*(__half2*)&u0.y);
        float2 b0 = __half22float2(*(__half2*)&u1.x), b1 = __half22float2(*(__half2*)&u1.y);
        float2 c0 = __half22float2(*(__half2*)&u2.x), c1 = __half22float2(*(__half2*)&u2.y);
        float2 t0 = __half22float2(*(__half2*)&ua.x), t1 = __half22float2(*(__half2*)&ua.y);
        float4 bv = bfr[idx];
        float4 x;
        x.x = a0.x + b0.x + c0.x + t0.x + bv.x;
        x.y = a0.y + b0.y + c0.y + t0.y + bv.y;
        x.z = a1.x + b1.x + c1.x + t1.x + bv.z;
        x.w = a1.y + b1.y + c1.y + t1.y + bv.w;
        v[i] = x;
        s  += x.x + x.y + x.z + x.w;
        s2 += x.x * x.x + x.y * x.y + x.z * x.z + x.w * x.w;
    }
    warp_reduce2(s, s2);
    float mean = s * (1.f / D_MODEL);
    float var = s2 * (1.f / D_MODEL) - mean * mean;
    float rstd = rsqrtf(var + LN_EPS);
    const float4* gr = reinterpret_cast<const float4*>(gam);
    const float4* br = reinterpret_cast<const float4*>(bet);
    float4* op = reinterpret_cast<float4*>(out) + rbase;
    #pragma unroll
    for (int i = 0; i < 6; i++) {
        int idx = lane + 32 * i;
        float4 g = gr[idx];
        float4 b = br[idx];
        float4 o;
        o.x = (v[i].x - mean) * rstd * g.x + b.x;
        o.y = (v[i].y - mean) * rstd * g.y + b.y;
        o.z = (v[i].z - mean) * rstd * g.z + b.z;
        o.w = (v[i].w - mean) * rstd * g.w + b.w;
        op[idx] = o;
    }
}

// ---------------- persistent GEMM, dynamic tiles, MIO-interleaved pipeline -------
// CTA tile 128x128, 128 threads (2x2 warps of 64x64), BK=64, 3-stage ring.
// cp.async split into 4 parts issued between mma half-bursts; cross-kt fragment
// preload after wait+bar.
// EPI==1: C = gelu(acc + bias) -> g_H              (K=768,  KT=12, 1536 tiles)
// EPI==2: split-K3, fp16 partials -> g_P/g_P2/g_P3 (Kc=1024, KT=16, 1152 tiles)
#define BK 64
#define LDT 72                        // padded smem row elems; 144B stride
#define TILE_B 18432                  // 128*72*2 per operand
#define STAGE_B 36864
#define NSTAGE 3
#define SMEM_GEMM (NSTAGE * STAGE_B + 16)

template <int EPI>
__global__ void __launch_bounds__(128, 2) gemm_kernel(const float* __restrict__ bias) {
    const __half* __restrict__ Ap = (EPI == 1) ? g_A : g_H;
    const __half* __restrict__ Bp = (EPI == 1) ? g_Wi : g_Wf;
    const int K  = (EPI == 1) ? D_MODEL : D_FF;
    const int NN = (EPI == 1) ? D_FF : D_MODEL;
    const int KT = (EPI == 1) ? 12 : 16;            // slabs per tile
    const int NT = (EPI == 1) ? 1536 : 1152;        // total tiles
    unsigned* ctr = (EPI == 1) ? &g_ctr1 : &g_ctr2;

    extern __shared__ char smem[];
    const uint32_t smem_u32 = (uint32_t)__cvta_generic_to_shared(smem);
    volatile unsigned* sm_next = (volatile unsigned*)(smem + NSTAGE * STAGE_B);

    const int tid = threadIdx.x;
    const int lane = tid & 31;
    const int warp = tid >> 5;
    const int wm = warp >> 1;
    const int wn = warp & 1;
    const int lrow = tid >> 3;        // 0..15
    const int lcol = tid & 7;         // 0..7

    __shared__ unsigned s_t0;
    if (tid == 0) s_t0 = atomicAdd(ctr, 1u);
    __syncthreads();
    unsigned t = s_t0;
    if (t >= (unsigned)NT) return;

    auto decode = [&](unsigned tt, int& mb, int& nb, int& kb) {
        if (EPI == 1) { nb = (tt % 24) * 128; mb = (tt / 24) * 128; kb = 0; }
        else          { nb = (tt % 6) * 128; mb = ((tt / 6) % 64) * 128; kb = (tt / 384) * 1024; }
    };

    int m_blk, n_blk, k_base;
    decode(t, m_blk, n_blk, k_base);

    const __half* pA = Ap + (size_t)(m_blk + lrow) * K + lcol * 8 + k_base;
    const __half* pB = Bp + (size_t)(n_blk + lrow) * K + lcol * 8 + k_base;

    const uint32_t sm_woff = (uint32_t)(lrow * 144 + lcol * 16);

    // one quarter (2x16 rows of A and B) of a BK=64 slab
    auto load_part = [&](int s, int koff, const __half* a, const __half* b, int part) {
        uint32_t base = smem_u32 + s * STAGE_B + sm_woff + (uint32_t)(part * 32 * 144);
        const __half* ga = a + (size_t)(part * 32) * K + koff;
        const __half* gb = b + (size_t)(part * 32) * K + koff;
        cp16(base,                       ga);
        cp16(base + TILE_B,              gb);
        cp16(base + 16 * 144,            ga + (size_t)16 * K);
        cp16(base + 16 * 144 + TILE_B,   gb + (size_t)16 * K);
    };

    const int a_row = wm * 64 + (lane & 15);
    const int a_k = (lane >> 4) * 8;
    const int b_row = wn * 64 + (lane & 7) + ((lane >> 4) & 1) * 8;
    const int b_k = ((lane >> 3) & 1) * 8;

    uint32_t aF[2][4][4], bF[2][4][4];
    auto ldsm_frags = [&](int buf, uint32_t base, int ks) {
        const int k0 = ks * 16;
        #pragma unroll
        for (int mt = 0; mt < 4; ++mt)
            ldsm4(aF[buf][mt], base + (uint32_t)((a_row + mt * 16) * LDT + k0 + a_k) * 2);
        #pragma unroll
        for (int np = 0; np < 4; ++np)
            ldsm4(bF[buf][np], base + TILE_B +
                                   (uint32_t)((b_row + np * 16) * LDT + k0 + b_k) * 2);
    };

    // preamble: slabs 0 and 1 of first tile; preload ks0 frags of slab 0
    #pragma unroll
    for (int p = 0; p < 4; ++p) load_part(0, 0, pA, pB, p);
    asm volatile("cp.async.commit_group;");
    #pragma unroll
    for (int p = 0; p < 4; ++p) load_part(1, BK, pA, pB, p);
    asm volatile("cp.async.commit_group;");
    asm volatile("cp.async.wait_group 1;");
    __syncthreads();
    ldsm_frags(0, smem_u32, 0);

    int cur_st = 0;
    for (;;) {
        if (tid == 0) sm_next[0] = atomicAdd(ctr, 1u);

        float acc[4][8][4];
        #pragma unroll
        for (int a = 0; a < 4; a++)
            #pragma unroll
            for (int b = 0; b < 8; b++)
                #pragma unroll
                for (int c = 0; c < 4; c++) acc[a][b][c] = 0.f;

        unsigned t_next = 0;
        bool has_next = false;
        int nm = 0, nn2 = 0, nk = 0;
        const __half *pAn = pA, *pBn = pB;

        for (int kt = 0; kt < KT; ++kt) {
            if (kt == KT - 2) {
                t_next = sm_next[0];
                has_next = t_next < (unsigned)NT;
                if (has_next) {
                    decode(t_next, nm, nn2, nk);
                    pAn = Ap + (size_t)(nm + lrow) * K + lcol * 8 + nk;
                    pBn = Bp + (size_t)(nn2 + lrow) * K + lcol * 8 + nk;
                }
            }

            const uint32_t base = smem_u32 + cur_st * STAGE_B;
            int p_st = cur_st + 2; if (p_st >= NSTAGE) p_st -= NSTAGE;
            const bool tail = (kt + 2 >= KT);
            const bool do_cp = !tail || has_next;
            const int koff = (tail ? (kt + 2 - KT) : (kt + 2)) * BK;
            const __half* qA = tail ? pAn : pA;
            const __half* qB = tail ? pBn : pB;

            #pragma unroll
            for (int ks = 0; ks < 4; ++ks) {
                const int cur = ks & 1;
                if (ks < 3) ldsm_frags(cur ^ 1, base, ks + 1);
                // first mma half-burst (mt 0..1)
                #pragma unroll
                for (int mt = 0; mt < 2; ++mt)
                    #pragma unroll
                    for (int nt = 0; nt < 8; ++nt) {
                        uint32_t b0 = bF[cur][nt >> 1][(nt & 1) * 2];
                        uint32_t b1 = bF[cur][nt >> 1][(nt & 1) * 2 + 1];
                        mma_f16(acc[mt][nt], aF[cur][mt], b0, b1);
                    }
                // cp.async for slab kt+2 overlaps with tensor-busy window
                if (do_cp) load_part(p_st, koff, qA, qB, ks);
                if (ks == 3) asm volatile("cp.async.commit_group;");
                // second mma half-burst (mt 2..3)
                #pragma unroll
                for (int mt = 2; mt < 4; ++mt)
                    #pragma unroll
                    for (int nt = 0; nt < 8; ++nt) {
                        uint32_t b0 = bF[cur][nt >> 1][(nt & 1) * 2];
                        uint32_t b1 = bF[cur][nt >> 1][(nt & 1) * 2 + 1];
                        mma_f16(acc[mt][nt], aF[cur][mt], b0, b1);
                    }
            }

            // slab kt+1 guaranteed complete; preload its ks0 fragments
            asm volatile("cp.async.wait_group 1;");
            __syncthreads();
            int nxt_st = cur_st + 1; if (nxt_st >= NSTAGE) nxt_st -= NSTAGE;
            if (kt + 1 < KT || has_next)
                ldsm_frags(0, smem_u32 + nxt_st * STAGE_B, 0);
            cur_st = nxt_st;
        }

        // ---------------- epilogue ----------------
        __half* Pout = g_P;
        if (EPI == 2) Pout = (k_base == 0) ? g_P : (k_base == 1024 ? g_P2 : g_P3);
        #pragma unroll
        for (int mt = 0; mt < 4; ++mt)
            #pragma unroll
            for (int nt = 0; nt < 8; ++nt) {
                int n = n_blk + wn * 64 + nt * 8 + (lane & 3) * 2;
                float b0 = 0.f, b1 = 0.f;
                if (EPI == 1) { b0 = bias[n]; b1 = bias[n + 1]; }
                #pragma unroll
                for (int h = 0; h < 2; ++h) {
                    int m = m_blk + wm * 64 + mt * 16 + (lane >> 2) + h * 8;
                    float x0 = acc[mt][nt][2 * h + 0] + b0;
                    float x1 = acc[mt][nt][2 * h + 1] + b1;
                    size_t o = (size_t)m * NN + n;
                    if (EPI == 1) {
                        __half2 hv = __floats2half2_rn(gelu_exact(x0), gelu_exact(x1));
                        *reinterpret_cast<__half2*>(&g_H[o]) = hv;
                    } else {
                        __half2 hv = __floats2half2_rn(x0, x1);
                        *reinterpret_cast<__half2*>(&Pout[o]) = hv;
                    }
                }
            }

        if (!has_next) break;
        t = t_next; m_blk = nm; n_blk = nn2; k_base = nk;
        pA = pAn; pB = pBn;
    }
}

// ---------------- launch ---------------------------------------------------------
extern "C" void kernel_launch(void* const* d_in, const int* in_sizes, int n_in,
                              void* d_out, int out_size) {
    (void)in_sizes; (void)n_in; (void)out_size;
    const float* hidden = (const float*)d_in[0];
    // d_in[1..6] = Wq,bq,Wk,bk,Wv,bv — dead (q/k/v overwritten by constants)
    const float* Wo   = (const float*)d_in[7];
    const float* bo   = (const float*)d_in[8];
    const float* ln1g = (const float*)d_in[9];
    const float* ln1b = (const float*)d_in[10];
    const float* Wi   = (const float*)d_in[11];
    const float* bi   = (const float*)d_in[12];
    const float* Wf   = (const float*)d_in[13];
    const float* bf_  = (const float*)d_in[14];
    const float* ln2g = (const float*)d_in[15];
    const float* ln2b = (const float*)d_in[16];
    float* out = (float*)d_out;

    cudaFuncSetAttribute(gemm_kernel<1>, cudaFuncAttributeMaxDynamicSharedMemorySize, SMEM_GEMM);
    cudaFuncSetAttribute(gemm_kernel<2>, cudaFuncAttributeMaxDynamicSharedMemorySize, SMEM_GEMM);

    rowsum_kernel<<<96, 256>>>(Wo, bo);
    prep_kernel<<<LN1_BLOCKS + CONV_BLOCKS, 256>>>(hidden, ln1g, ln1b, Wi, Wf);

    gemm_kernel<1><<<GRIDP, 128, SMEM_GEMM>>>(bi);
    gemm_kernel<2><<<GRIDP, 128, SMEM_GEMM>>>(bf_);

    ln2_kernel<<<MROWS / 8, 256>>>(ln2g, ln2b, bf_, out);
}

// round 13
// speedup vs baseline: 3.8864x; 1.0171x over previous
#include <cuda_runtime.h>
#include <cuda_fp16.h>
#include <stdint.h>

#define D_MODEL 768
#define D_FF    3072
#define MROWS   8192   // B*S = 4*2048
#define LN_EPS  1e-12f
#define GRIDP   296    // persistent CTA count (2 per SM on 148-SM die)

// ---------------- scratch (__device__ globals; no runtime allocation) ----------
__device__ float   g_c[D_MODEL];
__device__ __half  g_A[(size_t)MROWS * D_MODEL];    // LN1 output (also ln2 residual)
__device__ __half  g_Wi[(size_t)D_FF * D_MODEL];
__device__ __half  g_Wf[(size_t)D_MODEL * D_FF];
__device__ __half  g_H[(size_t)MROWS * D_FF];
__device__ __half  g_P[(size_t)MROWS * D_MODEL];
__device__ __half  g_P2[(size_t)MROWS * D_MODEL];
__device__ __half  g_P3[(size_t)MROWS * D_MODEL];
__device__ unsigned g_ctr1;
__device__ unsigned g_rowcnt[64];   // gemm1 completion counters per 128-row block

// ---------------- helpers --------------------------------------------------------
__device__ __forceinline__ float gelu_exact(float x) {
    return 0.5f * x * (1.0f + erff(x * 0.7071067811865476f));
}

__device__ __forceinline__ void ldsm4(uint32_t (&r)[4], uint32_t addr) {
    asm volatile("ldmatrix.sync.aligned.m8n8.x4.shared.b16 {%0,%1,%2,%3}, [%4];"
                 : "=r"(r[0]), "=r"(r[1]), "=r"(r[2]), "=r"(r[3])
                 : "r"(addr));
}

__device__ __forceinline__ void mma_f16(float (&c)[4], const uint32_t (&a)[4],
                                        uint32_t b0, uint32_t b1) {
    asm volatile(
        "mma.sync.aligned.m16n8k16.row.col.f32.f16.f16.f32 "
        "{%0,%1,%2,%3},{%4,%5,%6,%7},{%8,%9},{%0,%1,%2,%3};"
        : "+f"(c[0]), "+f"(c[1]), "+f"(c[2]), "+f"(c[3])
        : "r"(a[0]), "r"(a[1]), "r"(a[2]), "r"(a[3]), "r"(b0), "r"(b1));
}

__device__ __forceinline__ void cp16(uint32_t saddr, const void* g) {
    asm volatile("cp.async.cg.shared.global [%0], [%1], 16;" ::"r"(saddr), "l"(g));
}

// warp butterfly reduce (all lanes get result)
__device__ __forceinline__ void warp_reduce2(float& s, float& s2) {
    #pragma unroll
    for (int o = 16; o; o >>= 1) {
        s  += __shfl_xor_sync(0xffffffffu, s,  o);
        s2 += __shfl_xor_sync(0xffffffffu, s2, o);
    }
}

// ---------------- small kernels --------------------------------------------------
// also resets the dynamic-scheduler state each replay
__global__ void rowsum_kernel(const float* __restrict__ Wo, const float* __restrict__ bo) {
    if (blockIdx.x == 0) {
        if (threadIdx.x == 0) g_ctr1 = 0;
        if (threadIdx.x < 64) g_rowcnt[threadIdx.x] = 0;
    }
    int gw = (blockIdx.x * blockDim.x + threadIdx.x) >> 5;
    int lane = threadIdx.x & 31;
    if (gw >= D_MODEL) return;
    const float* r = Wo + (size_t)gw * D_MODEL;
    float s = 0.f;
    for (int j = lane; j < D_MODEL; j += 32) s += r[j];
    #pragma unroll
    for (int o = 16; o; o >>= 1) s += __shfl_down_sync(0xffffffffu, s, o);
    if (lane == 0) g_c[gw] = 0.01f * s + bo[gw];
}

// merged: blocks [0,1024) = ln1 (warp per row, 8 rows/block);
//         blocks [1024, 1024+4608) = weight conversion
#define LN1_BLOCKS  1024
#define CONV_BLOCKS 4608   // 2*(D_FF*D_MODEL/4)/256
__global__ void __launch_bounds__(256) prep_kernel(
        const float* __restrict__ hidden,
        const float* __restrict__ gam, const float* __restrict__ bet,
        const float* __restrict__ Wi, const float* __restrict__ Wf) {
    int bid = blockIdx.x;
    if (bid < LN1_BLOCKS) {
        int warp = threadIdx.x >> 5, lane = threadIdx.x & 31;
        int row = bid * 8 + warp;
        const float4* xr = reinterpret_cast<const float4*>(hidden + (size_t)row * D_MODEL);
        const float4* cr = reinterpret_cast<const float4*>(g_c);
        float4 v[6];
        float s = 0.f, s2 = 0.f;
        #pragma unroll
        for (int i = 0; i < 6; i++) {
            float4 x = xr[lane + 32 * i];
            float4 c = cr[lane + 32 * i];
            x.x += c.x; x.y += c.y; x.z += c.z; x.w += c.w;
            v[i] = x;
            s  += x.x + x.y + x.z + x.w;
            s2 += x.x * x.x + x.y * x.y + x.z * x.z + x.w * x.w;
        }
        warp_reduce2(s, s2);
        float mean = s * (1.f / D_MODEL);
        float var = s2 * (1.f / D_MODEL) - mean * mean;
        float rstd = rsqrtf(var + LN_EPS);
        uint2* outp = reinterpret_cast<uint2*>(g_A + (size_t)row * D_MODEL);
        const float4* gr = reinterpret_cast<const float4*>(gam);
        const float4* br = reinterpret_cast<const float4*>(bet);
        #pragma unroll
        for (int i = 0; i < 6; i++) {
            float4 g = gr[lane + 32 * i];
            float4 b = br[lane + 32 * i];
            float4 a;
            a.x = (v[i].x - mean) * rstd * g.x + b.x;
            a.y = (v[i].y - mean) * rstd * g.y + b.y;
            a.z = (v[i].z - mean) * rstd * g.z + b.z;
            a.w = (v[i].w - mean) * rstd * g.w + b.w;
            __half2 h0 = __floats2half2_rn(a.x, a.y);
            __half2 h1 = __floats2half2_rn(a.z, a.w);
            outp[lane + 32 * i] = make_uint2(*(uint32_t*)&h0, *(uint32_t*)&h1);
        }
    } else {
        constexpr int n4 = D_FF * D_MODEL / 4;
        int i = (bid - LN1_BLOCKS) * 256 + threadIdx.x;
        const float* src;
        __half* Wh;
        int j;
        if (i < n4) { src = Wi; Wh = g_Wi; j = i; }
        else        { src = Wf; Wh = g_Wf; j = i - n4; }
        float4 v = reinterpret_cast<const float4*>(src)[j];
        __half2 h01 = __floats2half2_rn(v.x, v.y);
        __half2 h23 = __floats2half2_rn(v.z, v.w);
        reinterpret_cast<uint2*>(Wh)[j] =
            make_uint2(*(uint32_t*)&h01, *(uint32_t*)&h23);
    }
}

// out = LN(P0 + P1 + P2 + A + bf); warp per row, 8 rows/block
__global__ void __launch_bounds__(256) ln2_kernel(
        const float* __restrict__ gam, const float* __restrict__ bet,
        const float* __restrict__ bf, float* __restrict__ out) {
    int warp = threadIdx.x >> 5, lane = threadIdx.x & 31;
    int row = blockIdx.x * 8 + warp;
    size_t rbase = (size_t)row * (D_MODEL / 4);
    const uint2* p0 = reinterpret_cast<const uint2*>(g_P)  + rbase;
    const uint2* p1 = reinterpret_cast<const uint2*>(g_P2) + rbase;
    const uint2* p2 = reinterpret_cast<const uint2*>(g_P3) + rbase;
    const uint2* pa = reinterpret_cast<const uint2*>(g_A)  + rbase;
    const float4* bfr = reinterpret_cast<const float4*>(bf);
    float4 v[6];
    float s = 0.f, s2 = 0.f;
    #pragma unroll
    for (int i = 0; i < 6; i++) {
        int idx = lane + 32 * i;
        uint2 u0 = p0[idx], u1 = p1[idx], u2 = p2[idx], ua = pa[idx];
        float2 a0 = __half22float2(*(__half2*)&u0.x), a1 = __half22float2(*(__half2*)&u0.y);
        float2 b0 = __half22float2(*(__half2*)&u1.x), b1 = __half22float2(*(__half2*)&u1.y);
        float2 c0 = __half22float2(*(__half2*)&u2.x), c1 = __half22float2(*(__half2*)&u2.y);
        float2 t0 = __half22float2(*(__half2*)&ua.x), t1 = __half22float2(*(__half2*)&ua.y);
        float4 bv = bfr[idx];
        float4 x;
        x.x = a0.x + b0.x + c0.x + t0.x + bv.x;
        x.y = a0.y + b0.y + c0.y + t0.y + bv.y;
        x.z = a1.x + b1.x + c1.x + t1.x + bv.z;
        x.w = a1.y + b1.y + c1.y + t1.y + bv.w;
        v[i] = x;
        s  += x.x + x.y + x.z + x.w;
        s2 += x.x * x.x + x.y * x.y + x.z * x.z + x.w * x.w;
    }
    warp_reduce2(s, s2);
    float mean = s * (1.f / D_MODEL);
    float var = s2 * (1.f / D_MODEL) - mean * mean;
    float rstd = rsqrtf(var + LN_EPS);
    const float4* gr = reinterpret_cast<const float4*>(gam);
    const float4* br = reinterpret_cast<const float4*>(bet);
    float4* op = reinterpret_cast<float4*>(out) + rbase;
    #pragma unroll
    for (int i = 0; i < 6; i++) {
        int idx = lane + 32 * i;
        float4 g = gr[idx];
        float4 b = br[idx];
        float4 o;
        o.x = (v[i].x - mean) * rstd * g.x + b.x;
        o.y = (v[i].y - mean) * rstd * g.y + b.y;
        o.z = (v[i].z - mean) * rstd * g.z + b.z;
        o.w = (v[i].w - mean) * rstd * g.w + b.w;
        op[idx] = o;
    }
}

// ---------------- fused persistent GEMM (both phases, one kernel) ----------------
// Tiles 0..1535:    gemm1  C = gelu(A@Wi^T + bi) -> g_H    (K=768,  KT=12)
// Tiles 1536..2687: gemm2  split-K3 fp16 partials -> g_P*  (Kc=1024, KT=16)
// Cross-phase dataflow guarded by g_rowcnt. The readiness check mid-tile is
// NON-BLOCKING; if not ready, the CTA finishes its tile (incl. its own rowcnt
// increment) and only then spins + refills -> provably deadlock-free.
#define BK 64
#define LDT 72                        // padded smem row elems; 144B stride
#define TILE_B 18432                  // 128*72*2 per operand
#define STAGE_B 36864
#define NSTAGE 3
#define SMEM_GEMM (NSTAGE * STAGE_B + 16)
#define NT1 1536
#define NT_ALL 2688

__global__ void __launch_bounds__(128, 2) gemm_fused(const float* __restrict__ bias1) {
    extern __shared__ char smem[];
    const uint32_t smem_u32 = (uint32_t)__cvta_generic_to_shared(smem);
    volatile unsigned* sm_next = (volatile unsigned*)(smem + NSTAGE * STAGE_B);
    volatile unsigned* sm_flag = (volatile unsigned*)(smem + NSTAGE * STAGE_B + 4);

    const int tid = threadIdx.x;
    const int lane = tid & 31;
    const int warp = tid >> 5;
    const int wm = warp >> 1;
    const int wn = warp & 1;
    const int lrow = tid >> 3;        // 0..15
    const int lcol = tid & 7;         // 0..7

    __shared__ unsigned s_t0;
    if (tid == 0) s_t0 = atomicAdd(&g_ctr1, 1u);
    __syncthreads();
    unsigned t = s_t0;
    if (t >= NT_ALL) return;

    auto decode = [&](unsigned tt, int& mb, int& nb, int& kb, int& kk, int& ktn, bool& is1) {
        if (tt < NT1) {
            is1 = true;  nb = (tt % 24) * 128; mb = (tt / 24) * 128; kb = 0;
            kk = D_MODEL; ktn = 12;
        } else {
            unsigned u = tt - NT1;
            is1 = false; nb = (u % 6) * 128; mb = ((u / 6) % 64) * 128; kb = (u / 384) * 1024;
            kk = D_FF; ktn = 16;
        }
    };

    int m_blk, n_blk, k_base, K, KT;
    bool is1;
    decode(t, m_blk, n_blk, k_base, K, KT, is1);   // first 296 tiles are all gemm1

    const __half* pA = (is1 ? g_A : g_H) + (size_t)(m_blk + lrow) * K + lcol * 8 + k_base;
    const __half* pB = (is1 ? g_Wi : g_Wf) + (size_t)(n_blk + lrow) * K + lcol * 8 + k_base;

    const uint32_t sm_woff = (uint32_t)(lrow * 144 + lcol * 16);

    // one quarter (2x16 rows of A and B) of a BK=64 slab; stride = row pitch (elems)
    auto load_part = [&](int s, int koff, const __half* a, const __half* b, int part,
                         int stride) {
        uint32_t base = smem_u32 + s * STAGE_B + sm_woff + (uint32_t)(part * 32 * 144);
        const __half* ga = a + (size_t)(part * 32) * stride + koff;
        const __half* gb = b + (size_t)(part * 32) * stride + koff;
        cp16(base,                       ga);
        cp16(base + TILE_B,              gb);
        cp16(base + 16 * 144,            ga + (size_t)16 * stride);
        cp16(base + 16 * 144 + TILE_B,   gb + (size_t)16 * stride);
    };

    const int a_row = wm * 64 + (lane & 15);
    const int a_k = (lane >> 4) * 8;
    const int b_row = wn * 64 + (lane & 7) + ((lane >> 4) & 1) * 8;
    const int b_k = ((lane >> 3) & 1) * 8;

    uint32_t aF[2][4][4], bF[2][4][4];
    auto ldsm_frags = [&](int buf, uint32_t base, int ks) {
        const int k0 = ks * 16;
        #pragma unroll
        for (int mt = 0; mt < 4; ++mt)
            ldsm4(aF[buf][mt], base + (uint32_t)((a_row + mt * 16) * LDT + k0 + a_k) * 2);
        #pragma unroll
        for (int np = 0; np < 4; ++np)
            ldsm4(bF[buf][np], base + TILE_B +
                                   (uint32_t)((b_row + np * 16) * LDT + k0 + b_k) * 2);
    };

    // preamble: slabs 0 and 1 of first tile; preload ks0 frags of slab 0
    #pragma unroll
    for (int p = 0; p < 4; ++p) load_part(0, 0, pA, pB, p, K);
    asm volatile("cp.async.commit_group;");
    #pragma unroll
    for (int p = 0; p < 4; ++p) load_part(1, BK, pA, pB, p, K);
    asm volatile("cp.async.commit_group;");
    asm volatile("cp.async.wait_group 1;");
    __syncthreads();
    ldsm_frags(0, smem_u32, 0);

    int cur_st = 0;
    for (;;) {
        if (tid == 0) sm_next[0] = atomicAdd(&g_ctr1, 1u);

        float acc[4][8][4];
        #pragma unroll
        for (int a = 0; a < 4; a++)
            #pragma unroll
            for (int b = 0; b < 8; b++)
                #pragma unroll
                for (int c = 0; c < 4; c++) acc[a][b][c] = 0.f;

        unsigned t_next = 0;
        bool has_next = false;
        bool prefetched = true;   // cross-tile prefetch happened for next tile
        int nm = 0, nn2 = 0, nk = 0, Kn = K, KTn = KT;
        bool is1n = is1;
        const __half *pAn = pA, *pBn = pB;

        for (int kt = 0; kt < KT; ++kt) {
            if (kt == KT - 2) {
                t_next = sm_next[0];
                has_next = t_next < NT_ALL;
                if (has_next) {
                    decode(t_next, nm, nn2, nk, Kn, KTn, is1n);
                    if (!is1n) {
                        // NON-BLOCKING readiness check (uniform via smem flag)
                        if (tid == 0)
                            sm_flag[0] = (g_rowcnt[nm >> 7] >= 24u) ? 1u : 0u;
                        __syncthreads();
                        prefetched = (sm_flag[0] != 0u);
                    }
                    pAn = (is1n ? g_A : g_H) + (size_t)(nm + lrow) * Kn + lcol * 8 + nk;
                    pBn = (is1n ? g_Wi : g_Wf) + (size_t)(nn2 + lrow) * Kn + lcol * 8 + nk;
                }
            }

            const uint32_t base = smem_u32 + cur_st * STAGE_B;
            int p_st = cur_st + 2; if (p_st >= NSTAGE) p_st -= NSTAGE;
            const bool tail = (kt + 2 >= KT);
            const bool do_cp = !tail || (has_next && prefetched);
            const int koff = (tail ? (kt + 2 - KT) : (kt + 2)) * BK;
            const __half* qA = tail ? pAn : pA;
            const __half* qB = tail ? pBn : pB;
            const int qK = tail ? Kn : K;

            #pragma unroll
            for (int ks = 0; ks < 4; ++ks) {
                const int cur = ks & 1;
                if (ks < 3) ldsm_frags(cur ^ 1, base, ks + 1);
                // first mma half-burst (mt 0..1)
                #pragma unroll
                for (int mt = 0; mt < 2; ++mt)
                    #pragma unroll
                    for (int nt = 0; nt < 8; ++nt) {
                        uint32_t b0 = bF[cur][nt >> 1][(nt & 1) * 2];
                        uint32_t b1 = bF[cur][nt >> 1][(nt & 1) * 2 + 1];
                        mma_f16(acc[mt][nt], aF[cur][mt], b0, b1);
                    }
                if (do_cp) load_part(p_st, koff, qA, qB, ks, qK);
                if (ks == 3) asm volatile("cp.async.commit_group;");
                // second mma half-burst (mt 2..3)
                #pragma unroll
                for (int mt = 2; mt < 4; ++mt)
                    #pragma unroll
                    for (int nt = 0; nt < 8; ++nt) {
                        uint32_t b0 = bF[cur][nt >> 1][(nt & 1) * 2];
                        uint32_t b1 = bF[cur][nt >> 1][(nt & 1) * 2 + 1];
                        mma_f16(acc[mt][nt], aF[cur][mt], b0, b1);
                    }
            }

            asm volatile("cp.async.wait_group 1;");
            __syncthreads();
            int nxt_st = cur_st + 1; if (nxt_st >= NSTAGE) nxt_st -= NSTAGE;
            if (kt + 1 < KT || (has_next && prefetched))
                ldsm_frags(0, smem_u32 + nxt_st * STAGE_B, 0);
            cur_st = nxt_st;
        }

        // ---------------- epilogue ----------------
        if (is1) {
            #pragma unroll
            for (int mt = 0; mt < 4; ++mt)
                #pragma unroll
                for (int nt = 0; nt < 8; ++nt) {
                    int n = n_blk + wn * 64 + nt * 8 + (lane & 3) * 2;
                    float b0 = bias1[n], b1 = bias1[n + 1];
                    #pragma unroll
                    for (int h = 0; h < 2; ++h) {
                        int m = m_blk + wm * 64 + mt * 16 + (lane >> 2) + h * 8;
                        float x0 = acc[mt][nt][2 * h + 0] + b0;
                        float x1 = acc[mt][nt][2 * h + 1] + b1;
                        __half2 hv = __floats2half2_rn(gelu_exact(x0), gelu_exact(x1));
                        *reinterpret_cast<__half2*>(&g_H[(size_t)m * D_FF + n]) = hv;
                    }
                }
            __threadfence();
            __syncthreads();
            if (tid == 0) atomicAdd(&g_rowcnt[m_blk >> 7], 1u);
        } else {
            __half* Pout = (k_base == 0) ? g_P : (k_base == 1024 ? g_P2 : g_P3);
            #pragma unroll
            for (int mt = 0; mt < 4; ++mt)
                #pragma unroll
                for (int nt = 0; nt < 8; ++nt) {
                    int n = n_blk + wn * 64 + nt * 8 + (lane & 3) * 2;
                    #pragma unroll
                    for (int h = 0; h < 2; ++h) {
                        int m = m_blk + wm * 64 + mt * 16 + (lane >> 2) + h * 8;
                        __half2 hv = __floats2half2_rn(acc[mt][nt][2 * h],
                                                       acc[mt][nt][2 * h + 1]);
                        *reinterpret_cast<__half2*>(&Pout[(size_t)m * D_MODEL + n]) = hv;
                    }
                }
        }

        if (!has_next) break;

        if (!prefetched) {
            // next tile is gemm2 whose inputs weren't ready mid-tile: spin AFTER
            // our own epilogue/increment (deadlock-free), then refill pipeline.
            volatile unsigned* rc = &g_rowcnt[nm >> 7];
            while (*rc < 24u) { }
            __threadfence();
            __syncthreads();
            int st1 = cur_st + 1; if (st1 >= NSTAGE) st1 -= NSTAGE;
            #pragma unroll
            for (int p = 0; p < 4; ++p) load_part(cur_st, 0, pAn, pBn, p, Kn);
            asm volatile("cp.async.commit_group;");
            #pragma unroll
            for (int p = 0; p < 4; ++p) load_part(st1, BK, pAn, pBn, p, Kn);
            asm volatile("cp.async.commit_group;");
            asm volatile("cp.async.wait_group 1;");
            __syncthreads();
            ldsm_frags(0, smem_u32 + cur_st * STAGE_B, 0);
        }

        t = t_next; m_blk = nm; n_blk = nn2; k_base = nk;
        K = Kn; KT = KTn; is1 = is1n;
        pA = pAn; pB = pBn;
    }
}

// ---------------- launch ---------------------------------------------------------
extern "C" void kernel_launch(void* const* d_in, const int* in_sizes, int n_in,
                              void* d_out, int out_size) {
    (void)in_sizes; (void)n_in; (void)out_size;
    const float* hidden = (const float*)d_in[0];
    // d_in[1..6] = Wq,bq,Wk,bk,Wv,bv — dead (q/k/v overwritten by constants)
    const float* Wo   = (const float*)d_in[7];
    const float* bo   = (const float*)d_in[8];
    const float* ln1g = (const float*)d_in[9];
    const float* ln1b = (const float*)d_in[10];
    const float* Wi   = (const float*)d_in[11];
    const float* bi   = (const float*)d_in[12];
    const float* Wf   = (const float*)d_in[13];
    const float* bf_  = (const float*)d_in[14];
    const float* ln2g = (const float*)d_in[15];
    const float* ln2b = (const float*)d_in[16];
    float* out = (float*)d_out;

    cudaFuncSetAttribute(gemm_fused, cudaFuncAttributeMaxDynamicSharedMemorySize, SMEM_GEMM);

    rowsum_kernel<<<96, 256>>>(Wo, bo);
    prep_kernel<<<LN1_BLOCKS + CONV_BLOCKS, 256>>>(hidden, ln1g, ln1b, Wi, Wf);

    gemm_fused<<<GRIDP, 128, SMEM_GEMM>>>(bi);

    ln2_kernel<<<MROWS / 8, 256>>>(ln2g, ln2b, bf_, out);
}